// round 1
// baseline (speedup 1.0000x reference)
#include <cuda_runtime.h>
#include <math.h>

#define T_   2048
#define H_   16
#define HD_  64
#define C_   1024
#define B_   2
#define PAD  68   // 64 + 4: keeps float4 alignment (68*4B % 16 == 0) and breaks bank conflicts

// Scratch (device globals: allocation-free per harness rules)
__device__ float g_qkv[(size_t)B_ * T_ * 3 * C_];   // [B*T, 3C]
__device__ float g_att[(size_t)B_ * T_ * C_];        // [B*T, C]

// ---------------------------------------------------------------------------
// C[M,N] = A[M,K] @ B[N,K]^T   (both row-major, K contiguous: "NT" gemm)
// 64x64 tile, BK=16, 256 threads, 4x4 per-thread micro-tile.
// ---------------------------------------------------------------------------
__global__ __launch_bounds__(256) void gemm_nt(const float* __restrict__ A,
                                               const float* __restrict__ Bm,
                                               float* __restrict__ Cm,
                                               int M, int N, int K) {
    __shared__ float As[16][PAD];   // As[k][m]
    __shared__ float Bs[16][PAD];   // Bs[k][n]

    const int tid = threadIdx.x;
    const int tx = tid & 15;
    const int ty = tid >> 4;
    const int m0 = blockIdx.y * 64;
    const int n0 = blockIdx.x * 64;

    // one float4 per thread per tile load: 64 rows x 4 float4/row
    const int lr = tid >> 2;          // 0..63
    const int lk = (tid & 3) << 2;    // 0,4,8,12

    float acc[4][4] = {};

    for (int kt = 0; kt < K; kt += 16) {
        float4 a = *(const float4*)(A  + (size_t)(m0 + lr) * K + kt + lk);
        float4 b = *(const float4*)(Bm + (size_t)(n0 + lr) * K + kt + lk);
        As[lk + 0][lr] = a.x; As[lk + 1][lr] = a.y;
        As[lk + 2][lr] = a.z; As[lk + 3][lr] = a.w;
        Bs[lk + 0][lr] = b.x; Bs[lk + 1][lr] = b.y;
        Bs[lk + 2][lr] = b.z; Bs[lk + 3][lr] = b.w;
        __syncthreads();

        #pragma unroll
        for (int kk = 0; kk < 16; kk++) {
            float4 a4 = *(const float4*)&As[kk][ty << 2];
            float4 b4 = *(const float4*)&Bs[kk][tx << 2];
            float av[4] = {a4.x, a4.y, a4.z, a4.w};
            float bv[4] = {b4.x, b4.y, b4.z, b4.w};
            #pragma unroll
            for (int i = 0; i < 4; i++)
                #pragma unroll
                for (int j = 0; j < 4; j++)
                    acc[i][j] = fmaf(av[i], bv[j], acc[i][j]);
        }
        __syncthreads();
    }

    #pragma unroll
    for (int i = 0; i < 4; i++) {
        float4 o = make_float4(acc[i][0], acc[i][1], acc[i][2], acc[i][3]);
        *(float4*)(Cm + (size_t)(m0 + (ty << 2) + i) * N + n0 + (tx << 2)) = o;
    }
}

// ---------------------------------------------------------------------------
// Flash attention, fp32. One CTA per (q-block of 64, head, batch).
// Online softmax, K-tile smem reused for the P tile.
// smem: Qt[d][r] | KP (Kt[d][c] -> Pt[k][r]) | Vs[k][d], each [64][PAD].
// ---------------------------------------------------------------------------
__global__ __launch_bounds__(256) void attn_kernel(const float* __restrict__ qkv,
                                                   float* __restrict__ y) {
    extern __shared__ float sm[];
    float* Qt = sm;                 // [64][PAD]  Qt[d][r]
    float* KP = sm + 64 * PAD;      // [64][PAD]  Kt[d][c], later Pt[k][r]
    float* Vs = sm + 2 * 64 * PAD;  // [64][PAD]  Vs[k][d]

    const int tid = threadIdx.x;
    const int tx = tid & 15;
    const int ty = tid >> 4;
    const int qb = blockIdx.x;
    const int h  = blockIdx.y;
    const int b  = blockIdx.z;

    const size_t row = 3 * C_;
    const float* qptr = qkv + (size_t)b * T_ * row + (size_t)h * HD_;
    const float* kptr = qptr + C_;
    const float* vptr = qptr + 2 * C_;

    // Load Q tile (64 rows x 64 d), transposed into Qt[d][r]
    #pragma unroll
    for (int it = 0; it < 4; it++) {
        int lin = it * 256 + tid;
        int r = lin >> 4;
        int d = (lin & 15) << 2;
        float4 v = *(const float4*)(qptr + (size_t)(qb * 64 + r) * row + d);
        Qt[(d + 0) * PAD + r] = v.x;
        Qt[(d + 1) * PAD + r] = v.y;
        Qt[(d + 2) * PAD + r] = v.z;
        Qt[(d + 3) * PAD + r] = v.w;
    }

    float mrow[4] = {-INFINITY, -INFINITY, -INFINITY, -INFINITY};
    float lrow[4] = {0.f, 0.f, 0.f, 0.f};
    float Oacc[4][4] = {};

    const float scale = 0.125f;   // 1/sqrt(64)

    for (int kb = 0; kb <= qb; kb++) {
        __syncthreads();   // previous iter finished reading KP/Vs (and Q stores visible)

        // Load K tile -> Kt[d][c], V tile -> Vs[k][d]
        #pragma unroll
        for (int it = 0; it < 4; it++) {
            int lin = it * 256 + tid;
            int r = lin >> 4;
            int d = (lin & 15) << 2;
            float4 kv = *(const float4*)(kptr + (size_t)(kb * 64 + r) * row + d);
            KP[(d + 0) * PAD + r] = kv.x;
            KP[(d + 1) * PAD + r] = kv.y;
            KP[(d + 2) * PAD + r] = kv.z;
            KP[(d + 3) * PAD + r] = kv.w;
            float4 vv = *(const float4*)(vptr + (size_t)(kb * 64 + r) * row + d);
            *(float4*)&Vs[r * PAD + d] = vv;
        }
        __syncthreads();

        // S = Q @ K^T (per-thread 4x4)
        float s[4][4] = {};
        #pragma unroll 8
        for (int d = 0; d < 64; d++) {
            float4 q4 = *(const float4*)&Qt[d * PAD + (ty << 2)];
            float4 k4 = *(const float4*)&KP[d * PAD + (tx << 2)];
            float qv[4] = {q4.x, q4.y, q4.z, q4.w};
            float kv[4] = {k4.x, k4.y, k4.z, k4.w};
            #pragma unroll
            for (int i = 0; i < 4; i++)
                #pragma unroll
                for (int j = 0; j < 4; j++)
                    s[i][j] = fmaf(qv[i], kv[j], s[i][j]);
        }

        // scale + causal mask (mask only relevant on the diagonal block)
        if (kb == qb) {
            #pragma unroll
            for (int i = 0; i < 4; i++) {
                int qg = (ty << 2) + i;
                #pragma unroll
                for (int j = 0; j < 4; j++) {
                    int kg = (tx << 2) + j;
                    s[i][j] = (kg > qg) ? -1e9f : s[i][j] * scale;
                }
            }
        } else {
            #pragma unroll
            for (int i = 0; i < 4; i++)
                #pragma unroll
                for (int j = 0; j < 4; j++)
                    s[i][j] *= scale;
        }

        // Online softmax: row max / rescale / exp / row sum
        float p[4][4];
        #pragma unroll
        for (int i = 0; i < 4; i++) {
            float v = s[i][0];
            v = fmaxf(v, s[i][1]); v = fmaxf(v, s[i][2]); v = fmaxf(v, s[i][3]);
            #pragma unroll
            for (int off = 8; off >= 1; off >>= 1)
                v = fmaxf(v, __shfl_xor_sync(0xffffffffu, v, off));
            float mn = fmaxf(mrow[i], v);
            float alpha = __expf(mrow[i] - mn);
            mrow[i] = mn;

            float srow = 0.f;
            #pragma unroll
            for (int j = 0; j < 4; j++) {
                p[i][j] = __expf(s[i][j] - mn);
                srow += p[i][j];
            }
            #pragma unroll
            for (int off = 8; off >= 1; off >>= 1)
                srow += __shfl_xor_sync(0xffffffffu, srow, off);
            lrow[i] = lrow[i] * alpha + srow;

            #pragma unroll
            for (int j = 0; j < 4; j++)
                Oacc[i][j] *= alpha;
        }

        __syncthreads();   // everyone done reading Kt; safe to overwrite with P

        // Write P transposed into KP: Pt[k][r], k = tx*4+j, r = ty*4+i
        #pragma unroll
        for (int j = 0; j < 4; j++) {
            float4 pc = make_float4(p[0][j], p[1][j], p[2][j], p[3][j]);
            *(float4*)&KP[((tx << 2) + j) * PAD + (ty << 2)] = pc;
        }
        __syncthreads();

        // O += P @ V
        #pragma unroll 8
        for (int k = 0; k < 64; k++) {
            float4 p4 = *(const float4*)&KP[k * PAD + (ty << 2)];
            float4 v4 = *(const float4*)&Vs[k * PAD + (tx << 2)];
            float pv[4] = {p4.x, p4.y, p4.z, p4.w};
            float vv[4] = {v4.x, v4.y, v4.z, v4.w};
            #pragma unroll
            for (int i = 0; i < 4; i++)
                #pragma unroll
                for (int j = 0; j < 4; j++)
                    Oacc[i][j] = fmaf(pv[i], vv[j], Oacc[i][j]);
        }
    }

    // Epilogue: normalize and write y[b, t, h*64 + d]
    #pragma unroll
    for (int i = 0; i < 4; i++) {
        float rl = 1.0f / lrow[i];
        float4 o = make_float4(Oacc[i][0] * rl, Oacc[i][1] * rl,
                               Oacc[i][2] * rl, Oacc[i][3] * rl);
        size_t t = (size_t)b * T_ + qb * 64 + (ty << 2) + i;
        *(float4*)(y + t * C_ + h * HD_ + (tx << 2)) = o;
    }
}

// ---------------------------------------------------------------------------
extern "C" void kernel_launch(void* const* d_in, const int* in_sizes, int n_in,
                              void* d_out, int out_size) {
    (void)in_sizes; (void)n_in; (void)out_size;
    const float* x      = (const float*)d_in[0];
    const float* w_qkv  = (const float*)d_in[1];
    const float* w_proj = (const float*)d_in[2];
    float* out = (float*)d_out;

    float *qkv, *att;
    cudaGetSymbolAddress((void**)&qkv, g_qkv);
    cudaGetSymbolAddress((void**)&att, g_att);

    const int M = B_ * T_;   // 4096
    const int smem = 3 * 64 * PAD * (int)sizeof(float);   // 52224 B

    static_assert(3 * 64 * PAD * 4 == 52224, "smem size");
    cudaFuncSetAttribute(attn_kernel, cudaFuncAttributeMaxDynamicSharedMemorySize, smem);

    // 1) qkv = x @ w_qkv^T       [4096, 3072]
    gemm_nt<<<dim3(3 * C_ / 64, M / 64), 256>>>(x, w_qkv, qkv, M, 3 * C_, C_);

    // 2) attention               [4096, 1024]
    attn_kernel<<<dim3(T_ / 64, H_, B_), 256, smem>>>(qkv, att);

    // 3) out = att @ w_proj^T    [4096, 1024]
    gemm_nt<<<dim3(C_ / 64, M / 64), 256>>>(att, w_proj, out, M, C_, C_);
}

// round 3
// speedup vs baseline: 1.2269x; 1.2269x over previous
#include <cuda_runtime.h>
#include <math.h>
#include <stdint.h>

#define T_   2048
#define H_   16
#define HD_  64
#define C_   1024
#define B_   2
#define PAD  68

// Scratch (device globals)
__device__ float g_qkv[(size_t)B_ * T_ * 3 * C_];   // [B*T, 3C]
__device__ float g_att[(size_t)B_ * T_ * C_];        // [B*T, C]

// ============================ helpers ============================
__device__ __forceinline__ uint32_t smem_u32(const void* p) {
    uint32_t a;
    asm("{ .reg .u64 t; cvta.to.shared.u64 t, %1; cvt.u32.u64 %0, t; }" : "=r"(a) : "l"(p));
    return a;
}
__device__ __forceinline__ float to_tf32(float a) {
    float r;
    asm("cvt.rna.tf32.f32 %0, %1;" : "=f"(r) : "f"(a));
    return r;
}
__device__ __forceinline__ void cp_async16(uint32_t saddr, const void* gaddr) {
    asm volatile("cp.async.cg.shared.global [%0], [%1], 16;" :: "r"(saddr), "l"(gaddr));
}
#define CP_COMMIT() asm volatile("cp.async.commit_group;" ::: "memory")
#define CP_WAIT(n)  asm volatile("cp.async.wait_group %0;" :: "n"(n) : "memory")

// D += A*B  (m16n8k8 tf32, row.col)
__device__ __forceinline__ void mma_tf32(float* d,
                                         uint32_t a0, uint32_t a1, uint32_t a2, uint32_t a3,
                                         uint32_t b0, uint32_t b1) {
    asm volatile(
        "mma.sync.aligned.m16n8k8.row.col.f32.tf32.tf32.f32 "
        "{%0,%1,%2,%3}, {%4,%5,%6,%7}, {%8,%9}, {%0,%1,%2,%3};"
        : "+f"(d[0]), "+f"(d[1]), "+f"(d[2]), "+f"(d[3])
        : "r"(a0), "r"(a1), "r"(a2), "r"(a3), "r"(b0), "r"(b1));
}

// ============================ tf32 3x-split GEMM ============================
// C[M,N] = A[M,K] @ B[N,K]^T, fp32 in/out.
// 128x128 CTA tile, BK=32, 8 warps (4m x 2n), warp tile 32x64.
#define BKF      32
#define LDSTR    36                      // smem row stride in floats (bank-conflict-free)
#define STAGE_F  (2 * 128 * LDSTR)       // A tile + B tile floats per stage = 9216
#define GEMM_SMEM (2 * STAGE_F * 4)      // 73728 B

__global__ __launch_bounds__(256) void gemm_mma(const float* __restrict__ A,
                                                const float* __restrict__ Bm,
                                                float* __restrict__ Cm,
                                                int M, int N, int K) {
    extern __shared__ float sm[];

    const int tid = threadIdx.x;
    const int wid = tid >> 5;
    const int lan = tid & 31;
    const int g   = lan >> 2;       // group 0..7
    const int t4  = lan & 3;        // thread-in-group 0..3
    const int wm  = wid >> 1;       // 0..3  -> 32-row slab
    const int wn  = wid & 1;        // 0..1  -> 64-col slab
    const int m0  = blockIdx.y * 128;
    const int n0  = blockIdx.x * 128;

    // cp.async task mapping: 128 rows x 8 segs of 16B, for A then B (2048 tasks, 8/thread)
    const uint32_t sb = smem_u32(sm);

    auto load_stage = [&](int s, int kt) {
        const float* Ag = A  + (size_t)m0 * K + (size_t)kt * BKF;
        const float* Bg = Bm + (size_t)n0 * K + (size_t)kt * BKF;
        uint32_t as = sb + s * STAGE_F * 4;
        uint32_t bs = as + 128 * LDSTR * 4;
        #pragma unroll
        for (int i = 0; i < 4; i++) {
            int task = i * 256 + tid;       // 0..1023
            int r   = task >> 3;
            int seg = task & 7;
            cp_async16(as + (r * LDSTR + seg * 4) * 4, Ag + (size_t)r * K + seg * 4);
            cp_async16(bs + (r * LDSTR + seg * 4) * 4, Bg + (size_t)r * K + seg * 4);
        }
    };

    float acc[2][8][4];
    #pragma unroll
    for (int mt = 0; mt < 2; mt++)
        #pragma unroll
        for (int nt = 0; nt < 8; nt++)
            #pragma unroll
            for (int i = 0; i < 4; i++) acc[mt][nt][i] = 0.f;

    const int nk = K / BKF;     // 32
    load_stage(0, 0); CP_COMMIT();
    load_stage(1, 1); CP_COMMIT();

    for (int kt = 0; kt < nk; kt++) {
        CP_WAIT(1);
        __syncthreads();

        const float* As = sm + (kt & 1) * STAGE_F;
        const float* Bs = As + 128 * LDSTR;

        #pragma unroll
        for (int ks = 0; ks < 4; ks++) {
            const int ko = ks * 8;

            // A fragments (2 m-tiles), split hi/lo
            uint32_t ah[2][4], al[2][4];
            #pragma unroll
            for (int mt = 0; mt < 2; mt++) {
                const int rm = wm * 32 + mt * 16 + g;
                float r0 = As[(rm)     * LDSTR + ko + t4];
                float r1 = As[(rm + 8) * LDSTR + ko + t4];
                float r2 = As[(rm)     * LDSTR + ko + t4 + 4];
                float r3 = As[(rm + 8) * LDSTR + ko + t4 + 4];
                float h;
                h = to_tf32(r0); ah[mt][0] = __float_as_uint(h); al[mt][0] = __float_as_uint(to_tf32(r0 - h));
                h = to_tf32(r1); ah[mt][1] = __float_as_uint(h); al[mt][1] = __float_as_uint(to_tf32(r1 - h));
                h = to_tf32(r2); ah[mt][2] = __float_as_uint(h); al[mt][2] = __float_as_uint(to_tf32(r2 - h));
                h = to_tf32(r3); ah[mt][3] = __float_as_uint(h); al[mt][3] = __float_as_uint(to_tf32(r3 - h));
            }
            // B fragments (8 n-tiles), split hi/lo
            uint32_t bh[8][2], bl[8][2];
            #pragma unroll
            for (int nt = 0; nt < 8; nt++) {
                const int rn = wn * 64 + nt * 8 + g;
                float r0 = Bs[rn * LDSTR + ko + t4];
                float r1 = Bs[rn * LDSTR + ko + t4 + 4];
                float h;
                h = to_tf32(r0); bh[nt][0] = __float_as_uint(h); bl[nt][0] = __float_as_uint(to_tf32(r0 - h));
                h = to_tf32(r1); bh[nt][1] = __float_as_uint(h); bl[nt][1] = __float_as_uint(to_tf32(r1 - h));
            }
            // 3x-split MMAs
            #pragma unroll
            for (int mt = 0; mt < 2; mt++)
                #pragma unroll
                for (int nt = 0; nt < 8; nt++) {
                    mma_tf32(acc[mt][nt], ah[mt][0], ah[mt][1], ah[mt][2], ah[mt][3], bh[nt][0], bh[nt][1]);
                    mma_tf32(acc[mt][nt], ah[mt][0], ah[mt][1], ah[mt][2], ah[mt][3], bl[nt][0], bl[nt][1]);
                    mma_tf32(acc[mt][nt], al[mt][0], al[mt][1], al[mt][2], al[mt][3], bh[nt][0], bh[nt][1]);
                }
        }

        __syncthreads();
        if (kt + 2 < nk) { load_stage(kt & 1, kt + 2); CP_COMMIT(); }
    }

    // Epilogue: c0/c1 -> (row, col..col+1), c2/c3 -> (row+8, col..col+1)
    #pragma unroll
    for (int mt = 0; mt < 2; mt++) {
        const int r0 = m0 + wm * 32 + mt * 16 + g;
        #pragma unroll
        for (int nt = 0; nt < 8; nt++) {
            const int c = n0 + wn * 64 + nt * 8 + t4 * 2;
            *(float2*)(Cm + (size_t)r0 * N + c)       = make_float2(acc[mt][nt][0], acc[mt][nt][1]);
            *(float2*)(Cm + (size_t)(r0 + 8) * N + c) = make_float2(acc[mt][nt][2], acc[mt][nt][3]);
        }
    }
}

// ============================ Flash attention (fp32 SIMT) ============================
__global__ __launch_bounds__(256) void attn_kernel(const float* __restrict__ qkv,
                                                   float* __restrict__ y) {
    extern __shared__ float sm[];
    float* Qt = sm;
    float* KP = sm + 64 * PAD;
    float* Vs = sm + 2 * 64 * PAD;

    const int tid = threadIdx.x;
    const int tx = tid & 15;
    const int ty = tid >> 4;
    const int qb = blockIdx.x;
    const int h  = blockIdx.y;
    const int b  = blockIdx.z;

    const size_t row = 3 * C_;
    const float* qptr = qkv + (size_t)b * T_ * row + (size_t)h * HD_;
    const float* kptr = qptr + C_;
    const float* vptr = qptr + 2 * C_;

    #pragma unroll
    for (int it = 0; it < 4; it++) {
        int lin = it * 256 + tid;
        int r = lin >> 4;
        int d = (lin & 15) << 2;
        float4 v = *(const float4*)(qptr + (size_t)(qb * 64 + r) * row + d);
        Qt[(d + 0) * PAD + r] = v.x;
        Qt[(d + 1) * PAD + r] = v.y;
        Qt[(d + 2) * PAD + r] = v.z;
        Qt[(d + 3) * PAD + r] = v.w;
    }

    float mrow[4] = {-INFINITY, -INFINITY, -INFINITY, -INFINITY};
    float lrow[4] = {0.f, 0.f, 0.f, 0.f};
    float Oacc[4][4] = {};
    const float scale = 0.125f;

    for (int kb = 0; kb <= qb; kb++) {
        __syncthreads();
        #pragma unroll
        for (int it = 0; it < 4; it++) {
            int lin = it * 256 + tid;
            int r = lin >> 4;
            int d = (lin & 15) << 2;
            float4 kv = *(const float4*)(kptr + (size_t)(kb * 64 + r) * row + d);
            KP[(d + 0) * PAD + r] = kv.x;
            KP[(d + 1) * PAD + r] = kv.y;
            KP[(d + 2) * PAD + r] = kv.z;
            KP[(d + 3) * PAD + r] = kv.w;
            float4 vv = *(const float4*)(vptr + (size_t)(kb * 64 + r) * row + d);
            *(float4*)&Vs[r * PAD + d] = vv;
        }
        __syncthreads();

        float s[4][4] = {};
        #pragma unroll 8
        for (int d = 0; d < 64; d++) {
            float4 q4 = *(const float4*)&Qt[d * PAD + (ty << 2)];
            float4 k4 = *(const float4*)&KP[d * PAD + (tx << 2)];
            float qv[4] = {q4.x, q4.y, q4.z, q4.w};
            float kv[4] = {k4.x, k4.y, k4.z, k4.w};
            #pragma unroll
            for (int i = 0; i < 4; i++)
                #pragma unroll
                for (int j = 0; j < 4; j++)
                    s[i][j] = fmaf(qv[i], kv[j], s[i][j]);
        }

        if (kb == qb) {
            #pragma unroll
            for (int i = 0; i < 4; i++) {
                int qg = (ty << 2) + i;
                #pragma unroll
                for (int j = 0; j < 4; j++) {
                    int kg = (tx << 2) + j;
                    s[i][j] = (kg > qg) ? -1e9f : s[i][j] * scale;
                }
            }
        } else {
            #pragma unroll
            for (int i = 0; i < 4; i++)
                #pragma unroll
                for (int j = 0; j < 4; j++)
                    s[i][j] *= scale;
        }

        float p[4][4];
        #pragma unroll
        for (int i = 0; i < 4; i++) {
            float v = s[i][0];
            v = fmaxf(v, s[i][1]); v = fmaxf(v, s[i][2]); v = fmaxf(v, s[i][3]);
            #pragma unroll
            for (int off = 8; off >= 1; off >>= 1)
                v = fmaxf(v, __shfl_xor_sync(0xffffffffu, v, off));
            float mn = fmaxf(mrow[i], v);
            float alpha = __expf(mrow[i] - mn);
            mrow[i] = mn;

            float srow = 0.f;
            #pragma unroll
            for (int j = 0; j < 4; j++) {
                p[i][j] = __expf(s[i][j] - mn);
                srow += p[i][j];
            }
            #pragma unroll
            for (int off = 8; off >= 1; off >>= 1)
                srow += __shfl_xor_sync(0xffffffffu, srow, off);
            lrow[i] = lrow[i] * alpha + srow;

            #pragma unroll
            for (int j = 0; j < 4; j++)
                Oacc[i][j] *= alpha;
        }

        __syncthreads();
        #pragma unroll
        for (int j = 0; j < 4; j++) {
            float4 pc = make_float4(p[0][j], p[1][j], p[2][j], p[3][j]);
            *(float4*)&KP[((tx << 2) + j) * PAD + (ty << 2)] = pc;
        }
        __syncthreads();

        #pragma unroll 8
        for (int k = 0; k < 64; k++) {
            float4 p4 = *(const float4*)&KP[k * PAD + (ty << 2)];
            float4 v4 = *(const float4*)&Vs[k * PAD + (tx << 2)];
            float pv[4] = {p4.x, p4.y, p4.z, p4.w};
            float vv[4] = {v4.x, v4.y, v4.z, v4.w};
            #pragma unroll
            for (int i = 0; i < 4; i++)
                #pragma unroll
                for (int j = 0; j < 4; j++)
                    Oacc[i][j] = fmaf(pv[i], vv[j], Oacc[i][j]);
        }
    }

    #pragma unroll
    for (int i = 0; i < 4; i++) {
        float rl = 1.0f / lrow[i];
        float4 o = make_float4(Oacc[i][0] * rl, Oacc[i][1] * rl,
                               Oacc[i][2] * rl, Oacc[i][3] * rl);
        size_t t = (size_t)b * T_ + qb * 64 + (ty << 2) + i;
        *(float4*)(y + t * C_ + h * HD_ + (tx << 2)) = o;
    }
}

// ============================ launch ============================
extern "C" void kernel_launch(void* const* d_in, const int* in_sizes, int n_in,
                              void* d_out, int out_size) {
    (void)in_sizes; (void)n_in; (void)out_size;
    const float* x      = (const float*)d_in[0];
    const float* w_qkv  = (const float*)d_in[1];
    const float* w_proj = (const float*)d_in[2];
    float* out = (float*)d_out;

    float *qkv, *att;
    cudaGetSymbolAddress((void**)&qkv, g_qkv);
    cudaGetSymbolAddress((void**)&att, g_att);

    const int M = B_ * T_;   // 4096
    const int attn_smem = 3 * 64 * PAD * (int)sizeof(float);

    cudaFuncSetAttribute(gemm_mma, cudaFuncAttributeMaxDynamicSharedMemorySize, GEMM_SMEM);
    cudaFuncSetAttribute(attn_kernel, cudaFuncAttributeMaxDynamicSharedMemorySize, attn_smem);

    // 1) qkv = x @ w_qkv^T     [4096, 3072]
    gemm_mma<<<dim3(3 * C_ / 128, M / 128), 256, GEMM_SMEM>>>(x, w_qkv, qkv, M, 3 * C_, C_);

    // 2) attention             [4096, 1024]
    attn_kernel<<<dim3(T_ / 64, H_, B_), 256, attn_smem>>>(qkv, att);

    // 3) out = att @ w_proj^T  [4096, 1024]
    gemm_mma<<<dim3(C_ / 128, M / 128), 256, GEMM_SMEM>>>(att, w_proj, out, M, C_, C_);
}

// round 4
// speedup vs baseline: 2.9778x; 2.4272x over previous
#include <cuda_runtime.h>
#include <cuda_bf16.h>
#include <math.h>
#include <stdint.h>

#define T_   2048
#define H_   16
#define HD_  64
#define C_   1024
#define B_   2
#define M_   (B_ * T_)          // 4096

// ===================== device scratch (bf16 hi/lo pairs) =====================
__device__ __nv_bfloat16 g_xh[(size_t)M_ * C_],      g_xl[(size_t)M_ * C_];
__device__ __nv_bfloat16 g_wqh[(size_t)3 * C_ * C_], g_wql[(size_t)3 * C_ * C_];
__device__ __nv_bfloat16 g_wph[(size_t)C_ * C_],     g_wpl[(size_t)C_ * C_];
__device__ __nv_bfloat16 g_qkvh[(size_t)M_ * 3 * C_], g_qkvl[(size_t)M_ * 3 * C_];
__device__ __nv_bfloat16 g_atth[(size_t)M_ * C_],    g_attl[(size_t)M_ * C_];

// ===================== helpers =====================
__device__ __forceinline__ uint32_t smem_u32(const void* p) {
    uint32_t a;
    asm("{ .reg .u64 t; cvta.to.shared.u64 t, %1; cvt.u32.u64 %0, t; }" : "=r"(a) : "l"(p));
    return a;
}
__device__ __forceinline__ void cp_async16(uint32_t saddr, const void* gaddr) {
    asm volatile("cp.async.cg.shared.global [%0], [%1], 16;" :: "r"(saddr), "l"(gaddr));
}
#define CP_COMMIT() asm volatile("cp.async.commit_group;" ::: "memory")
#define CP_WAIT(n)  asm volatile("cp.async.wait_group %0;" :: "n"(n) : "memory")

__device__ __forceinline__ void ldsm4(uint32_t* r, uint32_t a) {
    asm volatile("ldmatrix.sync.aligned.m8n8.x4.shared.b16 {%0,%1,%2,%3}, [%4];"
                 : "=r"(r[0]), "=r"(r[1]), "=r"(r[2]), "=r"(r[3]) : "r"(a));
}
__device__ __forceinline__ void ldsm4t(uint32_t* r, uint32_t a) {
    asm volatile("ldmatrix.sync.aligned.m8n8.x4.trans.shared.b16 {%0,%1,%2,%3}, [%4];"
                 : "=r"(r[0]), "=r"(r[1]), "=r"(r[2]), "=r"(r[3]) : "r"(a));
}
// D += A*B, m16n8k16 bf16 row.col
__device__ __forceinline__ void mma_bf16(float* d, const uint32_t* a, uint32_t b0, uint32_t b1) {
    asm volatile("mma.sync.aligned.m16n8k16.row.col.f32.bf16.bf16.f32 "
                 "{%0,%1,%2,%3}, {%4,%5,%6,%7}, {%8,%9}, {%0,%1,%2,%3};"
                 : "+f"(d[0]), "+f"(d[1]), "+f"(d[2]), "+f"(d[3])
                 : "r"(a[0]), "r"(a[1]), "r"(a[2]), "r"(a[3]), "r"(b0), "r"(b1));
}
__device__ __forceinline__ uint32_t packbf(float hi, float lo) {
    uint32_t r;
    asm("cvt.rn.bf16x2.f32 %0, %1, %2;" : "=r"(r) : "f"(hi), "f"(lo));
    return r;
}
__device__ __forceinline__ float bf_lo(uint32_t u) { return __uint_as_float(u << 16); }
__device__ __forceinline__ float bf_hi(uint32_t u) { return __uint_as_float(u & 0xffff0000u); }
__device__ __forceinline__ float ex2(float x) {
    float y; asm("ex2.approx.ftz.f32 %0, %1;" : "=f"(y) : "f"(x)); return y;
}

// ===================== split fp32 -> bf16 hi/lo =====================
__global__ void split_kernel(const float4* __restrict__ src,
                             uint2* __restrict__ dh, uint2* __restrict__ dl, int n4) {
    int i = blockIdx.x * blockDim.x + threadIdx.x;
    if (i >= n4) return;
    float4 v = src[i];
    uint32_t h0 = packbf(v.y, v.x);
    uint32_t h1 = packbf(v.w, v.z);
    float r0 = v.x - bf_lo(h0), r1 = v.y - bf_hi(h0);
    float r2 = v.z - bf_lo(h1), r3 = v.w - bf_hi(h1);
    dh[i] = make_uint2(h0, h1);
    dl[i] = make_uint2(packbf(r1, r0), packbf(r3, r2));
}

// ===================== bf16-3x GEMM: C = A(MxK) @ B(NxK)^T =====================
#define GSTR   144                    // smem row stride bytes (128 data + 16 pad)
#define GTILE  (128 * GSTR)           // 18432
#define GSTAGE (4 * GTILE)            // 73728
#define GEMM_SMEM (2 * GSTAGE)        // 147456

template<bool SPLIT_OUT>
__global__ __launch_bounds__(256) void gemm_bf16(
    const __nv_bfloat16* __restrict__ Ah, const __nv_bfloat16* __restrict__ Al,
    const __nv_bfloat16* __restrict__ Bh, const __nv_bfloat16* __restrict__ Bl,
    float* __restrict__ Cf, __nv_bfloat16* __restrict__ Ch, __nv_bfloat16* __restrict__ Cl,
    int M, int N, int K) {
    extern __shared__ char smc[];
    const uint32_t sb = smem_u32(smc);
    const int tid = threadIdx.x;
    const int wid = tid >> 5, lane = tid & 31;
    const int g = lane >> 2, t4 = lane & 3;
    const int i8 = lane & 7, mq = lane >> 3;
    const int wm = wid >> 1, wn = wid & 1;
    const int m0 = blockIdx.y * 128, n0 = blockIdx.x * 128;

    auto load_stage = [&](int s, int kt) {
        uint32_t base = sb + s * GSTAGE;
        #pragma unroll
        for (int it = 0; it < 16; it++) {
            int task = it * 256 + tid;                 // 0..4095
            int mat = task >> 10;
            int rem = task & 1023;
            int row = rem >> 3, ch = rem & 7;
            const __nv_bfloat16* gp = (mat == 0) ? Ah : (mat == 1) ? Al : (mat == 2) ? Bh : Bl;
            int grow = ((mat < 2) ? m0 : n0) + row;
            cp_async16(base + mat * GTILE + row * GSTR + ch * 16,
                       gp + (size_t)grow * K + kt * 64 + ch * 8);
        }
    };

    float acc[2][8][4];
    #pragma unroll
    for (int mt = 0; mt < 2; mt++)
        #pragma unroll
        for (int nt = 0; nt < 8; nt++)
            #pragma unroll
            for (int i = 0; i < 4; i++) acc[mt][nt][i] = 0.f;

    const int nk = K / 64;            // 16
    load_stage(0, 0); CP_COMMIT();
    load_stage(1, 1); CP_COMMIT();

    // ldmatrix lane-offset patterns
    const uint32_t aoff = (uint32_t)((wm * 32 + (mq & 1) * 8 + i8) * GSTR + (mq >> 1) * 16);
    const uint32_t boff = (uint32_t)((wn * 64 + (mq >> 1) * 8 + i8) * GSTR + (mq & 1) * 16);

    for (int kb = 0; kb < nk; kb++) {
        if (kb == nk - 1) { CP_WAIT(0); } else { CP_WAIT(1); }
        __syncthreads();

        uint32_t sA  = sb + (kb & 1) * GSTAGE;
        uint32_t sAl = sA + GTILE, sBh = sA + 2 * GTILE, sBl = sA + 3 * GTILE;

        #pragma unroll
        for (int kc = 0; kc < 4; kc++) {
            uint32_t ah[2][4], alr[2][4];
            #pragma unroll
            for (int mt = 0; mt < 2; mt++) {
                ldsm4(ah[mt],  sA  + aoff + mt * 16 * GSTR + kc * 32);
                ldsm4(alr[mt], sAl + aoff + mt * 16 * GSTR + kc * 32);
            }
            #pragma unroll
            for (int p = 0; p < 4; p++) {
                uint32_t bh4[4], bl4[4];
                ldsm4(bh4, sBh + boff + p * 16 * GSTR + kc * 32);
                ldsm4(bl4, sBl + boff + p * 16 * GSTR + kc * 32);
                #pragma unroll
                for (int mt = 0; mt < 2; mt++) {
                    mma_bf16(acc[mt][2 * p],     ah[mt],  bh4[0], bh4[1]);
                    mma_bf16(acc[mt][2 * p],     ah[mt],  bl4[0], bl4[1]);
                    mma_bf16(acc[mt][2 * p],     alr[mt], bh4[0], bh4[1]);
                    mma_bf16(acc[mt][2 * p + 1], ah[mt],  bh4[2], bh4[3]);
                    mma_bf16(acc[mt][2 * p + 1], ah[mt],  bl4[2], bl4[3]);
                    mma_bf16(acc[mt][2 * p + 1], alr[mt], bh4[2], bh4[3]);
                }
            }
        }
        __syncthreads();
        if (kb + 2 < nk) { load_stage(kb & 1, kb + 2); CP_COMMIT(); }
    }

    // epilogue
    #pragma unroll
    for (int mt = 0; mt < 2; mt++) {
        const int r0 = m0 + wm * 32 + mt * 16 + g;
        #pragma unroll
        for (int nt = 0; nt < 8; nt++) {
            const int c = n0 + wn * 64 + nt * 8 + 2 * t4;
            float v0 = acc[mt][nt][0], v1 = acc[mt][nt][1];
            float v2 = acc[mt][nt][2], v3 = acc[mt][nt][3];
            if (SPLIT_OUT) {
                uint32_t uh0 = packbf(v1, v0);
                uint32_t ul0 = packbf(v1 - bf_hi(uh0), v0 - bf_lo(uh0));
                uint32_t uh1 = packbf(v3, v2);
                uint32_t ul1 = packbf(v3 - bf_hi(uh1), v2 - bf_lo(uh1));
                *(uint32_t*)(Ch + (size_t)r0 * N + c)       = uh0;
                *(uint32_t*)(Cl + (size_t)r0 * N + c)       = ul0;
                *(uint32_t*)(Ch + (size_t)(r0 + 8) * N + c) = uh1;
                *(uint32_t*)(Cl + (size_t)(r0 + 8) * N + c) = ul1;
            } else {
                *(float2*)(Cf + (size_t)r0 * N + c)       = make_float2(v0, v1);
                *(float2*)(Cf + (size_t)(r0 + 8) * N + c) = make_float2(v2, v3);
            }
        }
    }
}

// ===================== flash attention, bf16-3x mma =====================
// Br=128 (8 warps x 16 rows), Bc=64. Q hi/lo in registers.
#define ASTR    144
#define ATILE   (64 * ASTR)           // 9216 (K/V tiles)
#define AQ      (128 * ASTR)          // 18432 (Q tile)
#define ASTAGE  (4 * ATILE)           // 36864
#define ATT_SMEM (2 * AQ + 2 * ASTAGE)  // 110592

__global__ __launch_bounds__(256) void attn_mma(
    const __nv_bfloat16* __restrict__ qkvh, const __nv_bfloat16* __restrict__ qkvl,
    __nv_bfloat16* __restrict__ oh, __nv_bfloat16* __restrict__ ol) {
    extern __shared__ char smc[];
    const uint32_t sb = smem_u32(smc);
    const int tid = threadIdx.x;
    const int w = tid >> 5, lane = tid & 31;
    const int g = lane >> 2, t4 = lane & 3;
    const int i8 = lane & 7, mq = lane >> 3;
    const int qblk = (int)gridDim.x - 1 - (int)blockIdx.x;   // heavy CTAs first
    const int h = blockIdx.y, b = blockIdx.z;
    const int nkt = 2 * qblk + 2;
    const float CS = 0.18033688011112042f;                   // 0.125 * log2(e)
    const float NEGINF = -INFINITY;

    auto load_q = [&]() {
        #pragma unroll
        for (int it = 0; it < 8; it++) {
            int task = it * 256 + tid;       // 0..2047
            int mat = task >> 10;            // 0 hi, 1 lo
            int rem = task & 1023;
            int row = rem >> 3, ch = rem & 7;
            const __nv_bfloat16* src = mat ? qkvl : qkvh;
            cp_async16(sb + mat * AQ + row * ASTR + ch * 16,
                       src + ((size_t)(b * T_ + qblk * 128 + row)) * (3 * C_) + h * HD_ + ch * 8);
        }
    };
    auto load_kv = [&](int s, int kt) {
        #pragma unroll
        for (int it = 0; it < 8; it++) {
            int task = it * 256 + tid;       // 0..2047
            int mat = task >> 9;             // 0 Kh, 1 Kl, 2 Vh, 3 Vl
            int rem = task & 511;
            int row = rem >> 3, ch = rem & 7;
            const __nv_bfloat16* src = (mat & 1) ? qkvl : qkvh;
            int colbase = ((mat < 2) ? C_ : 2 * C_) + h * HD_;
            cp_async16(sb + 2 * AQ + s * ASTAGE + mat * ATILE + row * ASTR + ch * 16,
                       src + ((size_t)(b * T_ + kt * 64 + row)) * (3 * C_) + colbase + ch * 8);
        }
    };

    load_q(); load_kv(0, 0); CP_COMMIT();
    load_kv(1, 1); CP_COMMIT();
    CP_WAIT(1);
    __syncthreads();

    // Q fragments -> registers (A-frag pattern)
    uint32_t qh[4][4], qlr[4][4];
    {
        const uint32_t qoff = (uint32_t)((w * 16 + (mq & 1) * 8 + i8) * ASTR + (mq >> 1) * 16);
        #pragma unroll
        for (int kc = 0; kc < 4; kc++) {
            ldsm4(qh[kc],  sb + qoff + kc * 32);
            ldsm4(qlr[kc], sb + AQ + qoff + kc * 32);
        }
    }

    const uint32_t koff = (uint32_t)(((mq >> 1) * 8 + i8) * ASTR + (mq & 1) * 16);
    const uint32_t voff = (uint32_t)(((mq & 1) * 8 + i8) * ASTR + (mq >> 1) * 16);

    float O[8][4];
    #pragma unroll
    for (int nt = 0; nt < 8; nt++)
        #pragma unroll
        for (int i = 0; i < 4; i++) O[nt][i] = 0.f;
    float mcs0 = NEGINF, mcs1 = NEGINF, lsum0 = 0.f, lsum1 = 0.f;
    const int qrow0 = qblk * 128 + w * 16 + g;
    const int qrow1 = qrow0 + 8;

    for (int kb = 0; kb < nkt; kb++) {
        if (kb > 0) {
            if (kb == nkt - 1) { CP_WAIT(0); } else { CP_WAIT(1); }
            __syncthreads();
        }
        uint32_t sKH = sb + 2 * AQ + (kb & 1) * ASTAGE;
        uint32_t sKL = sKH + ATILE, sVH = sKH + 2 * ATILE, sVL = sKH + 3 * ATILE;

        // ---- S = Q K^T (bf16-3x) ----
        float S[8][4];
        #pragma unroll
        for (int nt = 0; nt < 8; nt++)
            #pragma unroll
            for (int i = 0; i < 4; i++) S[nt][i] = 0.f;

        #pragma unroll
        for (int kc = 0; kc < 4; kc++) {
            #pragma unroll
            for (int p = 0; p < 4; p++) {
                uint32_t kh4[4], kl4[4];
                ldsm4(kh4, sKH + koff + p * 16 * ASTR + kc * 32);
                ldsm4(kl4, sKL + koff + p * 16 * ASTR + kc * 32);
                mma_bf16(S[2 * p],     qh[kc],  kh4[0], kh4[1]);
                mma_bf16(S[2 * p],     qh[kc],  kl4[0], kl4[1]);
                mma_bf16(S[2 * p],     qlr[kc], kh4[0], kh4[1]);
                mma_bf16(S[2 * p + 1], qh[kc],  kh4[2], kh4[3]);
                mma_bf16(S[2 * p + 1], qh[kc],  kl4[2], kl4[3]);
                mma_bf16(S[2 * p + 1], qlr[kc], kh4[2], kh4[3]);
            }
        }

        // ---- causal mask ----
        const int kbase = kb * 64;
        if (kbase + 63 > qrow0) {
            #pragma unroll
            for (int nt = 0; nt < 8; nt++) {
                int kc0 = kbase + nt * 8 + 2 * t4;
                if (kc0 > qrow0)     S[nt][0] = NEGINF;
                if (kc0 + 1 > qrow0) S[nt][1] = NEGINF;
                if (kc0 > qrow1)     S[nt][2] = NEGINF;
                if (kc0 + 1 > qrow1) S[nt][3] = NEGINF;
            }
        }

        // ---- online softmax (base-2, scaled) ----
        float mx0 = NEGINF, mx1 = NEGINF;
        #pragma unroll
        for (int nt = 0; nt < 8; nt++) {
            mx0 = fmaxf(mx0, fmaxf(S[nt][0], S[nt][1]));
            mx1 = fmaxf(mx1, fmaxf(S[nt][2], S[nt][3]));
        }
        mx0 = fmaxf(mx0, __shfl_xor_sync(0xffffffffu, mx0, 1));
        mx0 = fmaxf(mx0, __shfl_xor_sync(0xffffffffu, mx0, 2));
        mx1 = fmaxf(mx1, __shfl_xor_sync(0xffffffffu, mx1, 1));
        mx1 = fmaxf(mx1, __shfl_xor_sync(0xffffffffu, mx1, 2));
        float mn0 = fmaxf(mcs0, mx0 * CS);
        float mn1 = fmaxf(mcs1, mx1 * CS);
        float a0 = ex2(mcs0 - mn0);
        float a1 = ex2(mcs1 - mn1);
        mcs0 = mn0; mcs1 = mn1;

        float s0 = 0.f, s1 = 0.f;
        #pragma unroll
        for (int nt = 0; nt < 8; nt++) {
            S[nt][0] = ex2(fmaf(S[nt][0], CS, -mcs0)); s0 += S[nt][0];
            S[nt][1] = ex2(fmaf(S[nt][1], CS, -mcs0)); s0 += S[nt][1];
            S[nt][2] = ex2(fmaf(S[nt][2], CS, -mcs1)); s1 += S[nt][2];
            S[nt][3] = ex2(fmaf(S[nt][3], CS, -mcs1)); s1 += S[nt][3];
        }
        s0 += __shfl_xor_sync(0xffffffffu, s0, 1);
        s0 += __shfl_xor_sync(0xffffffffu, s0, 2);
        s1 += __shfl_xor_sync(0xffffffffu, s1, 1);
        s1 += __shfl_xor_sync(0xffffffffu, s1, 2);
        lsum0 = lsum0 * a0 + s0;
        lsum1 = lsum1 * a1 + s1;
        #pragma unroll
        for (int nt = 0; nt < 8; nt++) {
            O[nt][0] *= a0; O[nt][1] *= a0;
            O[nt][2] *= a1; O[nt][3] *= a1;
        }

        // ---- P (hi/lo a-frags, register-only) then O += P V ----
        #pragma unroll
        for (int j = 0; j < 4; j++) {
            uint32_t ph[4], plr[4];
            ph[0] = packbf(S[2 * j][1],     S[2 * j][0]);
            ph[1] = packbf(S[2 * j][3],     S[2 * j][2]);
            ph[2] = packbf(S[2 * j + 1][1], S[2 * j + 1][0]);
            ph[3] = packbf(S[2 * j + 1][3], S[2 * j + 1][2]);
            plr[0] = packbf(S[2 * j][1]     - bf_hi(ph[0]), S[2 * j][0]     - bf_lo(ph[0]));
            plr[1] = packbf(S[2 * j][3]     - bf_hi(ph[1]), S[2 * j][2]     - bf_lo(ph[1]));
            plr[2] = packbf(S[2 * j + 1][1] - bf_hi(ph[2]), S[2 * j + 1][0] - bf_lo(ph[2]));
            plr[3] = packbf(S[2 * j + 1][3] - bf_hi(ph[3]), S[2 * j + 1][2] - bf_lo(ph[3]));
            #pragma unroll
            for (int p = 0; p < 4; p++) {
                uint32_t vh4[4], vl4[4];
                ldsm4t(vh4, sVH + voff + j * 16 * ASTR + p * 32);
                ldsm4t(vl4, sVL + voff + j * 16 * ASTR + p * 32);
                mma_bf16(O[2 * p],     ph,  vh4[0], vh4[1]);
                mma_bf16(O[2 * p],     ph,  vl4[0], vl4[1]);
                mma_bf16(O[2 * p],     plr, vh4[0], vh4[1]);
                mma_bf16(O[2 * p + 1], ph,  vh4[2], vh4[3]);
                mma_bf16(O[2 * p + 1], ph,  vl4[2], vl4[3]);
                mma_bf16(O[2 * p + 1], plr, vh4[2], vh4[3]);
            }
        }

        __syncthreads();
        if (kb + 2 < nkt) { load_kv(kb & 1, kb + 2); CP_COMMIT(); }
    }

    // ---- epilogue: normalize, split to bf16 hi/lo, store ----
    const float rl0 = 1.0f / lsum0, rl1 = 1.0f / lsum1;
    const size_t r0 = (size_t)(b * T_ + qrow0);
    const size_t r1 = r0 + 8;
    #pragma unroll
    for (int nt = 0; nt < 8; nt++) {
        const int c = h * HD_ + nt * 8 + 2 * t4;
        float v0 = O[nt][0] * rl0, v1 = O[nt][1] * rl0;
        float v2 = O[nt][2] * rl1, v3 = O[nt][3] * rl1;
        uint32_t uh0 = packbf(v1, v0);
        uint32_t ul0 = packbf(v1 - bf_hi(uh0), v0 - bf_lo(uh0));
        uint32_t uh1 = packbf(v3, v2);
        uint32_t ul1 = packbf(v3 - bf_hi(uh1), v2 - bf_lo(uh1));
        *(uint32_t*)(oh + r0 * C_ + c) = uh0;
        *(uint32_t*)(ol + r0 * C_ + c) = ul0;
        *(uint32_t*)(oh + r1 * C_ + c) = uh1;
        *(uint32_t*)(ol + r1 * C_ + c) = ul1;
    }
}

// ===================== launch =====================
extern "C" void kernel_launch(void* const* d_in, const int* in_sizes, int n_in,
                              void* d_out, int out_size) {
    (void)in_sizes; (void)n_in; (void)out_size;
    const float* x      = (const float*)d_in[0];
    const float* w_qkv  = (const float*)d_in[1];
    const float* w_proj = (const float*)d_in[2];
    float* out = (float*)d_out;

    __nv_bfloat16 *xh, *xl, *wqh, *wql, *wph, *wpl, *qkvh, *qkvl, *atth, *attl;
    cudaGetSymbolAddress((void**)&xh, g_xh);     cudaGetSymbolAddress((void**)&xl, g_xl);
    cudaGetSymbolAddress((void**)&wqh, g_wqh);   cudaGetSymbolAddress((void**)&wql, g_wql);
    cudaGetSymbolAddress((void**)&wph, g_wph);   cudaGetSymbolAddress((void**)&wpl, g_wpl);
    cudaGetSymbolAddress((void**)&qkvh, g_qkvh); cudaGetSymbolAddress((void**)&qkvl, g_qkvl);
    cudaGetSymbolAddress((void**)&atth, g_atth); cudaGetSymbolAddress((void**)&attl, g_attl);

    cudaFuncSetAttribute(gemm_bf16<true>,  cudaFuncAttributeMaxDynamicSharedMemorySize, GEMM_SMEM);
    cudaFuncSetAttribute(gemm_bf16<false>, cudaFuncAttributeMaxDynamicSharedMemorySize, GEMM_SMEM);
    cudaFuncSetAttribute(attn_mma, cudaFuncAttributeMaxDynamicSharedMemorySize, ATT_SMEM);

    // 0) split inputs to bf16 hi/lo
    {
        int n4;
        n4 = M_ * C_ / 4;
        split_kernel<<<(n4 + 255) / 256, 256>>>((const float4*)x, (uint2*)xh, (uint2*)xl, n4);
        n4 = 3 * C_ * C_ / 4;
        split_kernel<<<(n4 + 255) / 256, 256>>>((const float4*)w_qkv, (uint2*)wqh, (uint2*)wql, n4);
        n4 = C_ * C_ / 4;
        split_kernel<<<(n4 + 255) / 256, 256>>>((const float4*)w_proj, (uint2*)wph, (uint2*)wpl, n4);
    }

    // 1) qkv = x @ w_qkv^T  -> split bf16 output
    gemm_bf16<true><<<dim3(3 * C_ / 128, M_ / 128), 256, GEMM_SMEM>>>(
        xh, xl, wqh, wql, nullptr, qkvh, qkvl, M_, 3 * C_, C_);

    // 2) attention -> split bf16 output
    attn_mma<<<dim3(T_ / 128, H_, B_), 256, ATT_SMEM>>>(qkvh, qkvl, atth, attl);

    // 3) out = att @ w_proj^T  (fp32 out)
    gemm_bf16<false><<<dim3(C_ / 128, M_ / 128), 256, GEMM_SMEM>>>(
        atth, attl, wph, wpl, out, nullptr, nullptr, M_, C_, C_);
}

// round 5
// speedup vs baseline: 4.3255x; 1.4526x over previous
#include <cuda_runtime.h>
#include <cuda_fp16.h>
#include <math.h>
#include <stdint.h>

#define T_   2048
#define H_   16
#define HD_  64
#define C_   1024
#define B_   2
#define M_   (B_ * T_)          // 4096

// ===================== device scratch (fp16) =====================
__device__ __half g_xh[(size_t)M_ * C_];                              // x single
__device__ __half g_wqh[(size_t)3 * C_ * C_], g_wql[(size_t)3 * C_ * C_];
__device__ __half g_wph[(size_t)C_ * C_],     g_wpl[(size_t)C_ * C_];
__device__ __half g_qkvh[(size_t)M_ * 3 * C_], g_qkvl[(size_t)M_ * 3 * C_];
__device__ __half g_atth[(size_t)M_ * C_];                            // att single

// ===================== helpers =====================
__device__ __forceinline__ uint32_t smem_u32(const void* p) {
    uint32_t a;
    asm("{ .reg .u64 t; cvta.to.shared.u64 t, %1; cvt.u32.u64 %0, t; }" : "=r"(a) : "l"(p));
    return a;
}
__device__ __forceinline__ void cp_async16(uint32_t saddr, const void* gaddr) {
    asm volatile("cp.async.cg.shared.global [%0], [%1], 16;" :: "r"(saddr), "l"(gaddr));
}
#define CP_COMMIT() asm volatile("cp.async.commit_group;" ::: "memory")
#define CP_WAIT(n)  asm volatile("cp.async.wait_group %0;" :: "n"(n) : "memory")

__device__ __forceinline__ void ldsm4(uint32_t* r, uint32_t a) {
    asm volatile("ldmatrix.sync.aligned.m8n8.x4.shared.b16 {%0,%1,%2,%3}, [%4];"
                 : "=r"(r[0]), "=r"(r[1]), "=r"(r[2]), "=r"(r[3]) : "r"(a));
}
__device__ __forceinline__ void ldsm4t(uint32_t* r, uint32_t a) {
    asm volatile("ldmatrix.sync.aligned.m8n8.x4.trans.shared.b16 {%0,%1,%2,%3}, [%4];"
                 : "=r"(r[0]), "=r"(r[1]), "=r"(r[2]), "=r"(r[3]) : "r"(a));
}
// D += A*B, m16n8k16 fp16 row.col, fp32 accumulate
__device__ __forceinline__ void mma_f16(float* d, const uint32_t* a, uint32_t b0, uint32_t b1) {
    asm volatile("mma.sync.aligned.m16n8k16.row.col.f32.f16.f16.f32 "
                 "{%0,%1,%2,%3}, {%4,%5,%6,%7}, {%8,%9}, {%0,%1,%2,%3};"
                 : "+f"(d[0]), "+f"(d[1]), "+f"(d[2]), "+f"(d[3])
                 : "r"(a[0]), "r"(a[1]), "r"(a[2]), "r"(a[3]), "r"(b0), "r"(b1));
}
// pack(first -> high half, second -> low half)  — same mapping validated in R4
__device__ __forceinline__ uint32_t packh(float hi, float lo) {
    uint32_t r;
    asm("cvt.rn.f16x2.f32 %0, %1, %2;" : "=r"(r) : "f"(hi), "f"(lo));
    return r;
}
__device__ __forceinline__ float h_lo(uint32_t u) {
    return __half2float(__ushort_as_half((unsigned short)(u & 0xffffu)));
}
__device__ __forceinline__ float h_hi(uint32_t u) {
    return __half2float(__ushort_as_half((unsigned short)(u >> 16)));
}
__device__ __forceinline__ float ex2(float x) {
    float y; asm("ex2.approx.ftz.f32 %0, %1;" : "=f"(y) : "f"(x)); return y;
}

// ===================== split fp32 -> fp16 =====================
__global__ void split1_kernel(const float4* __restrict__ src, uint2* __restrict__ dh, int n4) {
    int i = blockIdx.x * blockDim.x + threadIdx.x;
    if (i >= n4) return;
    float4 v = src[i];
    dh[i] = make_uint2(packh(v.y, v.x), packh(v.w, v.z));
}
__global__ void split2_kernel(const float4* __restrict__ src,
                              uint2* __restrict__ dh, uint2* __restrict__ dl, int n4) {
    int i = blockIdx.x * blockDim.x + threadIdx.x;
    if (i >= n4) return;
    float4 v = src[i];
    uint32_t h0 = packh(v.y, v.x);
    uint32_t h1 = packh(v.w, v.z);
    dh[i] = make_uint2(h0, h1);
    dl[i] = make_uint2(packh(v.y - h_hi(h0), v.x - h_lo(h0)),
                       packh(v.w - h_hi(h1), v.z - h_lo(h1)));
}

// ===================== fp16-2x GEMM: C = A(MxK) @ B(NxK)^T =====================
// A single fp16, B hi+lo fp16. 128x128 CTA tile, BK=64, 8 warps (4m x 2n).
#define GSTR   144                    // 128 data + 16 pad bytes
#define GTILE  (128 * GSTR)           // 18432
#define GSTAGE (3 * GTILE)            // 55296 (A, Bh, Bl)
#define GEMM_SMEM (2 * GSTAGE)        // 110592 -> 2 CTA/SM

template<bool SPLIT_OUT>
__global__ __launch_bounds__(256, 2) void gemm_f16(
    const __half* __restrict__ Ah,
    const __half* __restrict__ Bh, const __half* __restrict__ Bl,
    float* __restrict__ Cf, __half* __restrict__ Ch, __half* __restrict__ Cl,
    int M, int N, int K) {
    extern __shared__ char smc[];
    const uint32_t sb = smem_u32(smc);
    const int tid = threadIdx.x;
    const int wid = tid >> 5, lane = tid & 31;
    const int g = lane >> 2, t4 = lane & 3;
    const int i8 = lane & 7, mq = lane >> 3;
    const int wm = wid >> 1, wn = wid & 1;
    const int m0 = blockIdx.y * 128, n0 = blockIdx.x * 128;

    auto load_stage = [&](int s, int kt) {
        uint32_t base = sb + s * GSTAGE;
        #pragma unroll
        for (int it = 0; it < 12; it++) {
            int task = it * 256 + tid;                 // 0..3071
            int mat = task >> 10;                      // 0=A, 1=Bh, 2=Bl
            int rem = task & 1023;
            int row = rem >> 3, ch = rem & 7;
            const __half* gp = (mat == 0) ? Ah : (mat == 1) ? Bh : Bl;
            int grow = ((mat == 0) ? m0 : n0) + row;
            cp_async16(base + mat * GTILE + row * GSTR + ch * 16,
                       gp + (size_t)grow * K + kt * 64 + ch * 8);
        }
    };

    float acc[2][8][4];
    #pragma unroll
    for (int mt = 0; mt < 2; mt++)
        #pragma unroll
        for (int nt = 0; nt < 8; nt++)
            #pragma unroll
            for (int i = 0; i < 4; i++) acc[mt][nt][i] = 0.f;

    const int nk = K / 64;            // 16
    load_stage(0, 0); CP_COMMIT();
    load_stage(1, 1); CP_COMMIT();

    const uint32_t aoff = (uint32_t)((wm * 32 + (mq & 1) * 8 + i8) * GSTR + (mq >> 1) * 16);
    const uint32_t boff = (uint32_t)((wn * 64 + (mq >> 1) * 8 + i8) * GSTR + (mq & 1) * 16);

    for (int kb = 0; kb < nk; kb++) {
        if (kb == nk - 1) { CP_WAIT(0); } else { CP_WAIT(1); }
        __syncthreads();

        uint32_t sA  = sb + (kb & 1) * GSTAGE;
        uint32_t sBh = sA + GTILE, sBl = sA + 2 * GTILE;

        #pragma unroll
        for (int kc = 0; kc < 4; kc++) {
            uint32_t a[2][4];
            #pragma unroll
            for (int mt = 0; mt < 2; mt++)
                ldsm4(a[mt], sA + aoff + mt * 16 * GSTR + kc * 32);
            #pragma unroll
            for (int p = 0; p < 4; p++) {
                uint32_t bh4[4], bl4[4];
                ldsm4(bh4, sBh + boff + p * 16 * GSTR + kc * 32);
                ldsm4(bl4, sBl + boff + p * 16 * GSTR + kc * 32);
                #pragma unroll
                for (int mt = 0; mt < 2; mt++) {
                    mma_f16(acc[mt][2 * p],     a[mt], bh4[0], bh4[1]);
                    mma_f16(acc[mt][2 * p],     a[mt], bl4[0], bl4[1]);
                    mma_f16(acc[mt][2 * p + 1], a[mt], bh4[2], bh4[3]);
                    mma_f16(acc[mt][2 * p + 1], a[mt], bl4[2], bl4[3]);
                }
            }
        }
        __syncthreads();
        if (kb + 2 < nk) { load_stage(kb & 1, kb + 2); CP_COMMIT(); }
    }

    #pragma unroll
    for (int mt = 0; mt < 2; mt++) {
        const int r0 = m0 + wm * 32 + mt * 16 + g;
        #pragma unroll
        for (int nt = 0; nt < 8; nt++) {
            const int c = n0 + wn * 64 + nt * 8 + 2 * t4;
            float v0 = acc[mt][nt][0], v1 = acc[mt][nt][1];
            float v2 = acc[mt][nt][2], v3 = acc[mt][nt][3];
            if (SPLIT_OUT) {
                uint32_t uh0 = packh(v1, v0);
                uint32_t ul0 = packh(v1 - h_hi(uh0), v0 - h_lo(uh0));
                uint32_t uh1 = packh(v3, v2);
                uint32_t ul1 = packh(v3 - h_hi(uh1), v2 - h_lo(uh1));
                *(uint32_t*)(Ch + (size_t)r0 * N + c)       = uh0;
                *(uint32_t*)(Cl + (size_t)r0 * N + c)       = ul0;
                *(uint32_t*)(Ch + (size_t)(r0 + 8) * N + c) = uh1;
                *(uint32_t*)(Cl + (size_t)(r0 + 8) * N + c) = ul1;
            } else {
                *(float2*)(Cf + (size_t)r0 * N + c)       = make_float2(v0, v1);
                *(float2*)(Cf + (size_t)(r0 + 8) * N + c) = make_float2(v2, v3);
            }
        }
    }
}

// ===================== flash attention, fp16-2x mma =====================
// Br=128 (8 warps x 16 rows), Bc=64. Q single fp16 in regs; K,V hi+lo.
#define ASTR    144
#define ATILE   (64 * ASTR)             // 9216
#define AQ      (128 * ASTR)            // 18432 (Q, hi only)
#define ASTAGE  (4 * ATILE)             // 36864 (Kh,Kl,Vh,Vl)
#define ATT_SMEM (AQ + 2 * ASTAGE)      // 92160 -> 2 CTA/SM

__global__ __launch_bounds__(256, 2) void attn_mma(
    const __half* __restrict__ qkvh, const __half* __restrict__ qkvl,
    __half* __restrict__ oh) {
    extern __shared__ char smc[];
    const uint32_t sb = smem_u32(smc);
    const int tid = threadIdx.x;
    const int w = tid >> 5, lane = tid & 31;
    const int g = lane >> 2, t4 = lane & 3;
    const int i8 = lane & 7, mq = lane >> 3;
    const int qblk = (int)gridDim.x - 1 - (int)blockIdx.x;   // heavy CTAs first
    const int h = blockIdx.y, b = blockIdx.z;
    const int nkt = 2 * qblk + 2;
    const float CS = 0.18033688011112042f;                   // 0.125 * log2(e)
    const float NEGINF = -INFINITY;

    auto load_q = [&]() {
        #pragma unroll
        for (int it = 0; it < 4; it++) {
            int task = it * 256 + tid;       // 0..1023
            int row = task >> 3, ch = task & 7;
            cp_async16(sb + row * ASTR + ch * 16,
                       qkvh + ((size_t)(b * T_ + qblk * 128 + row)) * (3 * C_) + h * HD_ + ch * 8);
        }
    };
    auto load_kv = [&](int s, int kt) {
        #pragma unroll
        for (int it = 0; it < 8; it++) {
            int task = it * 256 + tid;       // 0..2047
            int mat = task >> 9;             // 0 Kh, 1 Kl, 2 Vh, 3 Vl
            int rem = task & 511;
            int row = rem >> 3, ch = rem & 7;
            const __half* src = (mat & 1) ? qkvl : qkvh;
            int colbase = ((mat < 2) ? C_ : 2 * C_) + h * HD_;
            cp_async16(sb + AQ + s * ASTAGE + mat * ATILE + row * ASTR + ch * 16,
                       src + ((size_t)(b * T_ + kt * 64 + row)) * (3 * C_) + colbase + ch * 8);
        }
    };

    load_q(); load_kv(0, 0); CP_COMMIT();
    load_kv(1, 1); CP_COMMIT();
    CP_WAIT(1);
    __syncthreads();

    uint32_t qh[4][4];
    {
        const uint32_t qoff = (uint32_t)((w * 16 + (mq & 1) * 8 + i8) * ASTR + (mq >> 1) * 16);
        #pragma unroll
        for (int kc = 0; kc < 4; kc++)
            ldsm4(qh[kc], sb + qoff + kc * 32);
    }

    const uint32_t koff = (uint32_t)(((mq >> 1) * 8 + i8) * ASTR + (mq & 1) * 16);
    const uint32_t voff = (uint32_t)(((mq & 1) * 8 + i8) * ASTR + (mq >> 1) * 16);

    float O[8][4];
    #pragma unroll
    for (int nt = 0; nt < 8; nt++)
        #pragma unroll
        for (int i = 0; i < 4; i++) O[nt][i] = 0.f;
    float mcs0 = NEGINF, mcs1 = NEGINF, lsum0 = 0.f, lsum1 = 0.f;
    const int qrow0 = qblk * 128 + w * 16 + g;
    const int qrow1 = qrow0 + 8;

    for (int kb = 0; kb < nkt; kb++) {
        if (kb > 0) {
            if (kb == nkt - 1) { CP_WAIT(0); } else { CP_WAIT(1); }
            __syncthreads();
        }
        uint32_t sKH = sb + AQ + (kb & 1) * ASTAGE;
        uint32_t sKL = sKH + ATILE, sVH = sKH + 2 * ATILE, sVL = sKH + 3 * ATILE;

        // ---- S = Q K^T (fp16-2x) ----
        float S[8][4];
        #pragma unroll
        for (int nt = 0; nt < 8; nt++)
            #pragma unroll
            for (int i = 0; i < 4; i++) S[nt][i] = 0.f;

        #pragma unroll
        for (int kc = 0; kc < 4; kc++) {
            #pragma unroll
            for (int p = 0; p < 4; p++) {
                uint32_t kh4[4], kl4[4];
                ldsm4(kh4, sKH + koff + p * 16 * ASTR + kc * 32);
                ldsm4(kl4, sKL + koff + p * 16 * ASTR + kc * 32);
                mma_f16(S[2 * p],     qh[kc], kh4[0], kh4[1]);
                mma_f16(S[2 * p],     qh[kc], kl4[0], kl4[1]);
                mma_f16(S[2 * p + 1], qh[kc], kh4[2], kh4[3]);
                mma_f16(S[2 * p + 1], qh[kc], kl4[2], kl4[3]);
            }
        }

        // ---- causal mask ----
        const int kbase = kb * 64;
        if (kbase + 63 > qrow0) {
            #pragma unroll
            for (int nt = 0; nt < 8; nt++) {
                int kc0 = kbase + nt * 8 + 2 * t4;
                if (kc0 > qrow0)     S[nt][0] = NEGINF;
                if (kc0 + 1 > qrow0) S[nt][1] = NEGINF;
                if (kc0 > qrow1)     S[nt][2] = NEGINF;
                if (kc0 + 1 > qrow1) S[nt][3] = NEGINF;
            }
        }

        // ---- online softmax (base-2) ----
        float mx0 = NEGINF, mx1 = NEGINF;
        #pragma unroll
        for (int nt = 0; nt < 8; nt++) {
            mx0 = fmaxf(mx0, fmaxf(S[nt][0], S[nt][1]));
            mx1 = fmaxf(mx1, fmaxf(S[nt][2], S[nt][3]));
        }
        mx0 = fmaxf(mx0, __shfl_xor_sync(0xffffffffu, mx0, 1));
        mx0 = fmaxf(mx0, __shfl_xor_sync(0xffffffffu, mx0, 2));
        mx1 = fmaxf(mx1, __shfl_xor_sync(0xffffffffu, mx1, 1));
        mx1 = fmaxf(mx1, __shfl_xor_sync(0xffffffffu, mx1, 2));
        float mn0 = fmaxf(mcs0, mx0 * CS);
        float mn1 = fmaxf(mcs1, mx1 * CS);
        float a0 = ex2(mcs0 - mn0);
        float a1 = ex2(mcs1 - mn1);
        mcs0 = mn0; mcs1 = mn1;

        float s0 = 0.f, s1 = 0.f;
        #pragma unroll
        for (int nt = 0; nt < 8; nt++) {
            S[nt][0] = ex2(fmaf(S[nt][0], CS, -mcs0)); s0 += S[nt][0];
            S[nt][1] = ex2(fmaf(S[nt][1], CS, -mcs0)); s0 += S[nt][1];
            S[nt][2] = ex2(fmaf(S[nt][2], CS, -mcs1)); s1 += S[nt][2];
            S[nt][3] = ex2(fmaf(S[nt][3], CS, -mcs1)); s1 += S[nt][3];
        }
        s0 += __shfl_xor_sync(0xffffffffu, s0, 1);
        s0 += __shfl_xor_sync(0xffffffffu, s0, 2);
        s1 += __shfl_xor_sync(0xffffffffu, s1, 1);
        s1 += __shfl_xor_sync(0xffffffffu, s1, 2);
        lsum0 = lsum0 * a0 + s0;
        lsum1 = lsum1 * a1 + s1;
        #pragma unroll
        for (int nt = 0; nt < 8; nt++) {
            O[nt][0] *= a0; O[nt][1] *= a0;
            O[nt][2] *= a1; O[nt][3] *= a1;
        }

        // ---- P (fp16 a-frags) then O += P V (V hi+lo) ----
        #pragma unroll
        for (int j = 0; j < 4; j++) {
            uint32_t ph[4];
            ph[0] = packh(S[2 * j][1],     S[2 * j][0]);
            ph[1] = packh(S[2 * j][3],     S[2 * j][2]);
            ph[2] = packh(S[2 * j + 1][1], S[2 * j + 1][0]);
            ph[3] = packh(S[2 * j + 1][3], S[2 * j + 1][2]);
            #pragma unroll
            for (int p = 0; p < 4; p++) {
                uint32_t vh4[4], vl4[4];
                ldsm4t(vh4, sVH + voff + j * 16 * ASTR + p * 32);
                ldsm4t(vl4, sVL + voff + j * 16 * ASTR + p * 32);
                mma_f16(O[2 * p],     ph, vh4[0], vh4[1]);
                mma_f16(O[2 * p],     ph, vl4[0], vl4[1]);
                mma_f16(O[2 * p + 1], ph, vh4[2], vh4[3]);
                mma_f16(O[2 * p + 1], ph, vl4[2], vl4[3]);
            }
        }

        __syncthreads();
        if (kb + 2 < nkt) { load_kv(kb & 1, kb + 2); CP_COMMIT(); }
    }

    // ---- epilogue: normalize, store fp16 (single copy) ----
    const float rl0 = 1.0f / lsum0, rl1 = 1.0f / lsum1;
    const size_t r0 = (size_t)(b * T_ + qrow0);
    const size_t r1 = r0 + 8;
    #pragma unroll
    for (int nt = 0; nt < 8; nt++) {
        const int c = h * HD_ + nt * 8 + 2 * t4;
        *(uint32_t*)(oh + r0 * C_ + c) = packh(O[nt][1] * rl0, O[nt][0] * rl0);
        *(uint32_t*)(oh + r1 * C_ + c) = packh(O[nt][3] * rl1, O[nt][2] * rl1);
    }
}

// ===================== launch =====================
extern "C" void kernel_launch(void* const* d_in, const int* in_sizes, int n_in,
                              void* d_out, int out_size) {
    (void)in_sizes; (void)n_in; (void)out_size;
    const float* x      = (const float*)d_in[0];
    const float* w_qkv  = (const float*)d_in[1];
    const float* w_proj = (const float*)d_in[2];
    float* out = (float*)d_out;

    __half *xh, *wqh, *wql, *wph, *wpl, *qkvh, *qkvl, *atth;
    cudaGetSymbolAddress((void**)&xh, g_xh);
    cudaGetSymbolAddress((void**)&wqh, g_wqh);   cudaGetSymbolAddress((void**)&wql, g_wql);
    cudaGetSymbolAddress((void**)&wph, g_wph);   cudaGetSymbolAddress((void**)&wpl, g_wpl);
    cudaGetSymbolAddress((void**)&qkvh, g_qkvh); cudaGetSymbolAddress((void**)&qkvl, g_qkvl);
    cudaGetSymbolAddress((void**)&atth, g_atth);

    cudaFuncSetAttribute(gemm_f16<true>,  cudaFuncAttributeMaxDynamicSharedMemorySize, GEMM_SMEM);
    cudaFuncSetAttribute(gemm_f16<false>, cudaFuncAttributeMaxDynamicSharedMemorySize, GEMM_SMEM);
    cudaFuncSetAttribute(attn_mma, cudaFuncAttributeMaxDynamicSharedMemorySize, ATT_SMEM);

    // 0) split inputs
    {
        int n4;
        n4 = M_ * C_ / 4;
        split1_kernel<<<(n4 + 255) / 256, 256>>>((const float4*)x, (uint2*)xh, n4);
        n4 = 3 * C_ * C_ / 4;
        split2_kernel<<<(n4 + 255) / 256, 256>>>((const float4*)w_qkv, (uint2*)wqh, (uint2*)wql, n4);
        n4 = C_ * C_ / 4;
        split2_kernel<<<(n4 + 255) / 256, 256>>>((const float4*)w_proj, (uint2*)wph, (uint2*)wpl, n4);
    }

    // 1) qkv = x @ w_qkv^T  -> hi/lo fp16
    gemm_f16<true><<<dim3(3 * C_ / 128, M_ / 128), 256, GEMM_SMEM>>>(
        xh, wqh, wql, nullptr, qkvh, qkvl, M_, 3 * C_, C_);

    // 2) attention -> fp16 (single)
    attn_mma<<<dim3(T_ / 128, H_, B_), 256, ATT_SMEM>>>(qkvh, qkvl, atth);

    // 3) out = att @ w_proj^T  (fp32 out)
    gemm_f16<false><<<dim3(C_ / 128, M_ / 128), 256, GEMM_SMEM>>>(
        atth, wph, wpl, out, nullptr, nullptr, M_, C_, C_);
}

// round 6
// speedup vs baseline: 4.6081x; 1.0653x over previous
#include <cuda_runtime.h>
#include <cuda_fp16.h>
#include <math.h>
#include <stdint.h>

#define T_   2048
#define H_   16
#define HD_  64
#define C_   1024
#define B_   2
#define M_   (B_ * T_)          // 4096

// ===================== device scratch (fp16) =====================
__device__ __half g_xh[(size_t)M_ * C_];                              // x single
__device__ __half g_wqh[(size_t)3 * C_ * C_], g_wql[(size_t)3 * C_ * C_];
__device__ __half g_wph[(size_t)C_ * C_],     g_wpl[(size_t)C_ * C_];
__device__ __half g_qkvh[(size_t)M_ * 3 * C_], g_qkvl[(size_t)M_ * 3 * C_];
__device__ __half g_atth[(size_t)M_ * C_];                            // att single

// ===================== helpers =====================
__device__ __forceinline__ uint32_t smem_u32(const void* p) {
    uint32_t a;
    asm("{ .reg .u64 t; cvta.to.shared.u64 t, %1; cvt.u32.u64 %0, t; }" : "=r"(a) : "l"(p));
    return a;
}
__device__ __forceinline__ void cp_async16(uint32_t saddr, const void* gaddr) {
    asm volatile("cp.async.cg.shared.global [%0], [%1], 16;" :: "r"(saddr), "l"(gaddr));
}
#define CP_COMMIT() asm volatile("cp.async.commit_group;" ::: "memory")
#define CP_WAIT(n)  asm volatile("cp.async.wait_group %0;" :: "n"(n) : "memory")

__device__ __forceinline__ void ldsm4(uint32_t* r, uint32_t a) {
    asm volatile("ldmatrix.sync.aligned.m8n8.x4.shared.b16 {%0,%1,%2,%3}, [%4];"
                 : "=r"(r[0]), "=r"(r[1]), "=r"(r[2]), "=r"(r[3]) : "r"(a));
}
__device__ __forceinline__ void ldsm4t(uint32_t* r, uint32_t a) {
    asm volatile("ldmatrix.sync.aligned.m8n8.x4.trans.shared.b16 {%0,%1,%2,%3}, [%4];"
                 : "=r"(r[0]), "=r"(r[1]), "=r"(r[2]), "=r"(r[3]) : "r"(a));
}
__device__ __forceinline__ void mma_f16(float* d, const uint32_t* a, uint32_t b0, uint32_t b1) {
    asm volatile("mma.sync.aligned.m16n8k16.row.col.f32.f16.f16.f32 "
                 "{%0,%1,%2,%3}, {%4,%5,%6,%7}, {%8,%9}, {%0,%1,%2,%3};"
                 : "+f"(d[0]), "+f"(d[1]), "+f"(d[2]), "+f"(d[3])
                 : "r"(a[0]), "r"(a[1]), "r"(a[2]), "r"(a[3]), "r"(b0), "r"(b1));
}
__device__ __forceinline__ uint32_t packh(float hi, float lo) {
    uint32_t r;
    asm("cvt.rn.f16x2.f32 %0, %1, %2;" : "=r"(r) : "f"(hi), "f"(lo));
    return r;
}
__device__ __forceinline__ float h_lo(uint32_t u) {
    return __half2float(__ushort_as_half((unsigned short)(u & 0xffffu)));
}
__device__ __forceinline__ float h_hi(uint32_t u) {
    return __half2float(__ushort_as_half((unsigned short)(u >> 16)));
}
__device__ __forceinline__ float ex2(float x) {
    float y; asm("ex2.approx.ftz.f32 %0, %1;" : "=f"(y) : "f"(x)); return y;
}

// ===================== split fp32 -> fp16 =====================
__global__ void split1_kernel(const float4* __restrict__ src, uint2* __restrict__ dh, int n4) {
    int i = blockIdx.x * blockDim.x + threadIdx.x;
    if (i >= n4) return;
    float4 v = src[i];
    dh[i] = make_uint2(packh(v.y, v.x), packh(v.w, v.z));
}
__global__ void split2_kernel(const float4* __restrict__ src,
                              uint2* __restrict__ dh, uint2* __restrict__ dl, int n4) {
    int i = blockIdx.x * blockDim.x + threadIdx.x;
    if (i >= n4) return;
    float4 v = src[i];
    uint32_t h0 = packh(v.y, v.x);
    uint32_t h1 = packh(v.w, v.z);
    dh[i] = make_uint2(h0, h1);
    dl[i] = make_uint2(packh(v.y - h_hi(h0), v.x - h_lo(h0)),
                       packh(v.w - h_hi(h1), v.z - h_lo(h1)));
}

// ===================== fp16-2x GEMM: C = A(MxK) @ B(NxK)^T =====================
// A single fp16, B hi+lo fp16. 128x128 CTA tile, BK=32, 3-stage ring, 1 barrier/iter.
#define GSTR   80                     // 64 data + 16 pad bytes per 32-col row
#define GTILE  (128 * GSTR)           // 10240
#define GSTAGE (3 * GTILE)            // 30720 (A, Bh, Bl)
#define GEMM_SMEM (3 * GSTAGE)        // 92160 -> 2 CTA/SM

template<bool SPLIT_OUT>
__global__ __launch_bounds__(256, 2) void gemm_f16(
    const __half* __restrict__ Ah,
    const __half* __restrict__ Bh, const __half* __restrict__ Bl,
    float* __restrict__ Cf, __half* __restrict__ Ch, __half* __restrict__ Cl,
    int M, int N, int K) {
    extern __shared__ char smc[];
    const uint32_t sb = smem_u32(smc);
    const int tid = threadIdx.x;
    const int wid = tid >> 5, lane = tid & 31;
    const int g = lane >> 2, t4 = lane & 3;
    const int i8 = lane & 7, mq = lane >> 3;
    const int wm = wid >> 1, wn = wid & 1;
    const int m0 = blockIdx.y * 128, n0 = blockIdx.x * 128;

    auto load_stage = [&](int s, int kt) {
        uint32_t base = sb + s * GSTAGE;
        #pragma unroll
        for (int it = 0; it < 6; it++) {
            int task = it * 256 + tid;                 // 0..1535
            int mat = task >> 9;                       // 0=A, 1=Bh, 2=Bl
            int rem = task & 511;
            int row = rem >> 2, ch = rem & 3;
            const __half* gp = (mat == 0) ? Ah : (mat == 1) ? Bh : Bl;
            int grow = ((mat == 0) ? m0 : n0) + row;
            cp_async16(base + mat * GTILE + row * GSTR + ch * 16,
                       gp + (size_t)grow * K + kt * 32 + ch * 8);
        }
    };

    float acc[2][8][4];
    #pragma unroll
    for (int mt = 0; mt < 2; mt++)
        #pragma unroll
        for (int nt = 0; nt < 8; nt++)
            #pragma unroll
            for (int i = 0; i < 4; i++) acc[mt][nt][i] = 0.f;

    const int nk = K / 32;            // 32
    load_stage(0, 0); CP_COMMIT();
    load_stage(1, 1); CP_COMMIT();

    const uint32_t aoff = (uint32_t)((wm * 32 + (mq & 1) * 8 + i8) * GSTR + (mq >> 1) * 16);
    const uint32_t boff = (uint32_t)((wn * 64 + (mq >> 1) * 8 + i8) * GSTR + (mq & 1) * 16);

    int s = 0, ls = 2;                // compute stage, load stage
    for (int kb = 0; kb < nk; kb++) {
        CP_WAIT(1);
        __syncthreads();

        uint32_t sA  = sb + s * GSTAGE;
        uint32_t sBh = sA + GTILE, sBl = sA + 2 * GTILE;

        #pragma unroll
        for (int kc = 0; kc < 2; kc++) {
            uint32_t a[2][4];
            #pragma unroll
            for (int mt = 0; mt < 2; mt++)
                ldsm4(a[mt], sA + aoff + mt * 16 * GSTR + kc * 32);
            #pragma unroll
            for (int p = 0; p < 4; p++) {
                uint32_t bh4[4], bl4[4];
                ldsm4(bh4, sBh + boff + p * 16 * GSTR + kc * 32);
                ldsm4(bl4, sBl + boff + p * 16 * GSTR + kc * 32);
                #pragma unroll
                for (int mt = 0; mt < 2; mt++) {
                    mma_f16(acc[mt][2 * p],     a[mt], bh4[0], bh4[1]);
                    mma_f16(acc[mt][2 * p],     a[mt], bl4[0], bl4[1]);
                    mma_f16(acc[mt][2 * p + 1], a[mt], bh4[2], bh4[3]);
                    mma_f16(acc[mt][2 * p + 1], a[mt], bl4[2], bl4[3]);
                }
            }
        }

        if (kb + 2 < nk) load_stage(ls, kb + 2);
        CP_COMMIT();                  // uniform group count (empty in tail)
        s  = (s  == 2) ? 0 : s + 1;
        ls = (ls == 2) ? 0 : ls + 1;
    }

    #pragma unroll
    for (int mt = 0; mt < 2; mt++) {
        const int r0 = m0 + wm * 32 + mt * 16 + g;
        #pragma unroll
        for (int nt = 0; nt < 8; nt++) {
            const int c = n0 + wn * 64 + nt * 8 + 2 * t4;
            float v0 = acc[mt][nt][0], v1 = acc[mt][nt][1];
            float v2 = acc[mt][nt][2], v3 = acc[mt][nt][3];
            if (SPLIT_OUT) {
                uint32_t uh0 = packh(v1, v0);
                uint32_t ul0 = packh(v1 - h_hi(uh0), v0 - h_lo(uh0));
                uint32_t uh1 = packh(v3, v2);
                uint32_t ul1 = packh(v3 - h_hi(uh1), v2 - h_lo(uh1));
                *(uint32_t*)(Ch + (size_t)r0 * N + c)       = uh0;
                *(uint32_t*)(Cl + (size_t)r0 * N + c)       = ul0;
                *(uint32_t*)(Ch + (size_t)(r0 + 8) * N + c) = uh1;
                *(uint32_t*)(Cl + (size_t)(r0 + 8) * N + c) = ul1;
            } else {
                *(float2*)(Cf + (size_t)r0 * N + c)       = make_float2(v0, v1);
                *(float2*)(Cf + (size_t)(r0 + 8) * N + c) = make_float2(v2, v3);
            }
        }
    }
}

// ===================== flash attention, fp16-2x mma =====================
// Br=128 (8 warps x 16 rows), Bc=64. Q single fp16; K,V hi+lo.
// Swizzled 128B rows (no pad): 3-stage KV ring, 1 barrier/iter.
#define ATILE   (64 * 128)              // 8192
#define AQ      (128 * 128)             // 16384 (Q, hi only)
#define ASTAGE  (4 * ATILE)             // 32768 (Kh,Kl,Vh,Vl)
#define ATT_SMEM (AQ + 3 * ASTAGE)      // 114688 -> 2 CTA/SM

__global__ __launch_bounds__(256, 2) void attn_mma(
    const __half* __restrict__ qkvh, const __half* __restrict__ qkvl,
    __half* __restrict__ oh) {
    extern __shared__ char smc[];
    const uint32_t sb = smem_u32(smc);
    const int tid = threadIdx.x;
    const int w = tid >> 5, lane = tid & 31;
    const int g = lane >> 2, t4 = lane & 3;
    const int i8 = lane & 7, mq = lane >> 3;
    const int qblk = (int)gridDim.x - 1 - (int)blockIdx.x;   // heavy CTAs first
    const int h = blockIdx.y, b = blockIdx.z;
    const int nkt = 2 * qblk + 2;
    const float CS = 0.18033688011112042f;                   // 0.125 * log2(e)
    const float NEGINF = -INFINITY;

    auto load_q = [&]() {
        #pragma unroll
        for (int it = 0; it < 4; it++) {
            int task = it * 256 + tid;       // 0..1023
            int row = task >> 3, ch = task & 7;
            cp_async16(sb + row * 128 + ((ch ^ (row & 7)) * 16),
                       qkvh + ((size_t)(b * T_ + qblk * 128 + row)) * (3 * C_) + h * HD_ + ch * 8);
        }
    };
    auto load_kv = [&](int s, int kt) {
        #pragma unroll
        for (int it = 0; it < 8; it++) {
            int task = it * 256 + tid;       // 0..2047
            int mat = task >> 9;             // 0 Kh, 1 Kl, 2 Vh, 3 Vl
            int rem = task & 511;
            int row = rem >> 3, ch = rem & 7;
            const __half* src = (mat & 1) ? qkvl : qkvh;
            int colbase = ((mat < 2) ? C_ : 2 * C_) + h * HD_;
            cp_async16(sb + AQ + s * ASTAGE + mat * ATILE + row * 128 + ((ch ^ (row & 7)) * 16),
                       src + ((size_t)(b * T_ + kt * 64 + row)) * (3 * C_) + colbase + ch * 8);
        }
    };

    load_q(); load_kv(0, 0); CP_COMMIT();
    load_kv(1, 1); CP_COMMIT();
    CP_WAIT(1);
    __syncthreads();

    // Q fragments (rows: w*16 + (mq&1)*8 + i8 -> row&7 == i8)
    uint32_t qh[4][4];
    {
        const uint32_t qrow = (uint32_t)((w * 16 + (mq & 1) * 8 + i8) * 128);
        #pragma unroll
        for (int kc = 0; kc < 4; kc++)
            ldsm4(qh[kc], sb + qrow + ((((mq >> 1) + 2 * kc) ^ i8) * 16));
    }

    float O[8][4];
    #pragma unroll
    for (int nt = 0; nt < 8; nt++)
        #pragma unroll
        for (int i = 0; i < 4; i++) O[nt][i] = 0.f;
    float mcs0 = NEGINF, mcs1 = NEGINF, lsum0 = 0.f, lsum1 = 0.f;
    const int qrow0 = qblk * 128 + w * 16 + g;
    const int qrow1 = qrow0 + 8;

    const uint32_t krow = (uint32_t)(((mq >> 1) * 8 + i8) * 128);    // + p*16*128
    const uint32_t vrow = (uint32_t)(((mq & 1) * 8 + i8) * 128);     // + j*16*128

    int st = 0, ls = 2;
    for (int kb = 0; kb < nkt; kb++) {
        if (kb > 0) {
            CP_WAIT(1);
            __syncthreads();
        }
        uint32_t sKH = sb + AQ + st * ASTAGE;
        uint32_t sKL = sKH + ATILE, sVH = sKH + 2 * ATILE, sVL = sKH + 3 * ATILE;

        // ---- S = Q K^T (fp16-2x) ----
        float S[8][4];
        #pragma unroll
        for (int nt = 0; nt < 8; nt++)
            #pragma unroll
            for (int i = 0; i < 4; i++) S[nt][i] = 0.f;

        #pragma unroll
        for (int kc = 0; kc < 4; kc++) {
            const uint32_t kcol = (uint32_t)((((mq & 1) + 2 * kc) ^ i8) * 16);
            #pragma unroll
            for (int p = 0; p < 4; p++) {
                uint32_t kh4[4], kl4[4];
                ldsm4(kh4, sKH + krow + p * 16 * 128 + kcol);
                ldsm4(kl4, sKL + krow + p * 16 * 128 + kcol);
                mma_f16(S[2 * p],     qh[kc], kh4[0], kh4[1]);
                mma_f16(S[2 * p],     qh[kc], kl4[0], kl4[1]);
                mma_f16(S[2 * p + 1], qh[kc], kh4[2], kh4[3]);
                mma_f16(S[2 * p + 1], qh[kc], kl4[2], kl4[3]);
            }
        }

        // ---- causal mask ----
        const int kbase = kb * 64;
        if (kbase + 63 > qrow0) {
            #pragma unroll
            for (int nt = 0; nt < 8; nt++) {
                int kc0 = kbase + nt * 8 + 2 * t4;
                if (kc0 > qrow0)     S[nt][0] = NEGINF;
                if (kc0 + 1 > qrow0) S[nt][1] = NEGINF;
                if (kc0 > qrow1)     S[nt][2] = NEGINF;
                if (kc0 + 1 > qrow1) S[nt][3] = NEGINF;
            }
        }

        // ---- online softmax (base-2) ----
        float mx0 = NEGINF, mx1 = NEGINF;
        #pragma unroll
        for (int nt = 0; nt < 8; nt++) {
            mx0 = fmaxf(mx0, fmaxf(S[nt][0], S[nt][1]));
            mx1 = fmaxf(mx1, fmaxf(S[nt][2], S[nt][3]));
        }
        mx0 = fmaxf(mx0, __shfl_xor_sync(0xffffffffu, mx0, 1));
        mx0 = fmaxf(mx0, __shfl_xor_sync(0xffffffffu, mx0, 2));
        mx1 = fmaxf(mx1, __shfl_xor_sync(0xffffffffu, mx1, 1));
        mx1 = fmaxf(mx1, __shfl_xor_sync(0xffffffffu, mx1, 2));
        float mn0 = fmaxf(mcs0, mx0 * CS);
        float mn1 = fmaxf(mcs1, mx1 * CS);
        float a0 = ex2(mcs0 - mn0);
        float a1 = ex2(mcs1 - mn1);
        mcs0 = mn0; mcs1 = mn1;

        float s0 = 0.f, s1 = 0.f;
        #pragma unroll
        for (int nt = 0; nt < 8; nt++) {
            S[nt][0] = ex2(fmaf(S[nt][0], CS, -mcs0)); s0 += S[nt][0];
            S[nt][1] = ex2(fmaf(S[nt][1], CS, -mcs0)); s0 += S[nt][1];
            S[nt][2] = ex2(fmaf(S[nt][2], CS, -mcs1)); s1 += S[nt][2];
            S[nt][3] = ex2(fmaf(S[nt][3], CS, -mcs1)); s1 += S[nt][3];
        }
        s0 += __shfl_xor_sync(0xffffffffu, s0, 1);
        s0 += __shfl_xor_sync(0xffffffffu, s0, 2);
        s1 += __shfl_xor_sync(0xffffffffu, s1, 1);
        s1 += __shfl_xor_sync(0xffffffffu, s1, 2);
        lsum0 = lsum0 * a0 + s0;
        lsum1 = lsum1 * a1 + s1;
        #pragma unroll
        for (int nt = 0; nt < 8; nt++) {
            O[nt][0] *= a0; O[nt][1] *= a0;
            O[nt][2] *= a1; O[nt][3] *= a1;
        }

        // ---- P (fp16 a-frags) then O += P V (V hi+lo) ----
        #pragma unroll
        for (int j = 0; j < 4; j++) {
            uint32_t ph[4];
            ph[0] = packh(S[2 * j][1],     S[2 * j][0]);
            ph[1] = packh(S[2 * j][3],     S[2 * j][2]);
            ph[2] = packh(S[2 * j + 1][1], S[2 * j + 1][0]);
            ph[3] = packh(S[2 * j + 1][3], S[2 * j + 1][2]);
            #pragma unroll
            for (int p = 0; p < 4; p++) {
                const uint32_t vcol = (uint32_t)((((mq >> 1) + 2 * p) ^ i8) * 16);
                uint32_t vh4[4], vl4[4];
                ldsm4t(vh4, sVH + vrow + j * 16 * 128 + vcol);
                ldsm4t(vl4, sVL + vrow + j * 16 * 128 + vcol);
                mma_f16(O[2 * p],     ph, vh4[0], vh4[1]);
                mma_f16(O[2 * p],     ph, vl4[0], vl4[1]);
                mma_f16(O[2 * p + 1], ph, vh4[2], vh4[3]);
                mma_f16(O[2 * p + 1], ph, vl4[2], vl4[3]);
            }
        }

        if (kb + 2 < nkt) load_kv(ls, kb + 2);
        CP_COMMIT();                      // uniform group count
        st = (st == 2) ? 0 : st + 1;
        ls = (ls == 2) ? 0 : ls + 1;
    }

    // ---- epilogue ----
    const float rl0 = 1.0f / lsum0, rl1 = 1.0f / lsum1;
    const size_t r0 = (size_t)(b * T_ + qrow0);
    const size_t r1 = r0 + 8;
    #pragma unroll
    for (int nt = 0; nt < 8; nt++) {
        const int c = h * HD_ + nt * 8 + 2 * t4;
        *(uint32_t*)(oh + r0 * C_ + c) = packh(O[nt][1] * rl0, O[nt][0] * rl0);
        *(uint32_t*)(oh + r1 * C_ + c) = packh(O[nt][3] * rl1, O[nt][2] * rl1);
    }
}

// ===================== launch =====================
extern "C" void kernel_launch(void* const* d_in, const int* in_sizes, int n_in,
                              void* d_out, int out_size) {
    (void)in_sizes; (void)n_in; (void)out_size;
    const float* x      = (const float*)d_in[0];
    const float* w_qkv  = (const float*)d_in[1];
    const float* w_proj = (const float*)d_in[2];
    float* out = (float*)d_out;

    __half *xh, *wqh, *wql, *wph, *wpl, *qkvh, *qkvl, *atth;
    cudaGetSymbolAddress((void**)&xh, g_xh);
    cudaGetSymbolAddress((void**)&wqh, g_wqh);   cudaGetSymbolAddress((void**)&wql, g_wql);
    cudaGetSymbolAddress((void**)&wph, g_wph);   cudaGetSymbolAddress((void**)&wpl, g_wpl);
    cudaGetSymbolAddress((void**)&qkvh, g_qkvh); cudaGetSymbolAddress((void**)&qkvl, g_qkvl);
    cudaGetSymbolAddress((void**)&atth, g_atth);

    cudaFuncSetAttribute(gemm_f16<true>,  cudaFuncAttributeMaxDynamicSharedMemorySize, GEMM_SMEM);
    cudaFuncSetAttribute(gemm_f16<false>, cudaFuncAttributeMaxDynamicSharedMemorySize, GEMM_SMEM);
    cudaFuncSetAttribute(attn_mma, cudaFuncAttributeMaxDynamicSharedMemorySize, ATT_SMEM);

    // 0) split inputs
    {
        int n4;
        n4 = M_ * C_ / 4;
        split1_kernel<<<(n4 + 255) / 256, 256>>>((const float4*)x, (uint2*)xh, n4);
        n4 = 3 * C_ * C_ / 4;
        split2_kernel<<<(n4 + 255) / 256, 256>>>((const float4*)w_qkv, (uint2*)wqh, (uint2*)wql, n4);
        n4 = C_ * C_ / 4;
        split2_kernel<<<(n4 + 255) / 256, 256>>>((const float4*)w_proj, (uint2*)wph, (uint2*)wpl, n4);
    }

    // 1) qkv = x @ w_qkv^T  -> hi/lo fp16
    gemm_f16<true><<<dim3(3 * C_ / 128, M_ / 128), 256, GEMM_SMEM>>>(
        xh, wqh, wql, nullptr, qkvh, qkvl, M_, 3 * C_, C_);

    // 2) attention -> fp16 (single)
    attn_mma<<<dim3(T_ / 128, H_, B_), 256, ATT_SMEM>>>(qkvh, qkvl, atth);

    // 3) out = att @ w_proj^T  (fp32 out)
    gemm_f16<false><<<dim3(C_ / 128, M_ / 128), 256, GEMM_SMEM>>>(
        atth, wph, wpl, out, nullptr, nullptr, M_, C_, C_);
}

// round 7
// speedup vs baseline: 4.8902x; 1.0612x over previous
#include <cuda_runtime.h>
#include <cuda_fp16.h>
#include <math.h>
#include <stdint.h>

#define T_   2048
#define H_   16
#define HD_  64
#define C_   1024
#define B_   2
#define M_   (B_ * T_)          // 4096

// ===================== device scratch (fp16) =====================
__device__ __half g_xh[(size_t)M_ * C_];                              // x single
__device__ __half g_wqh[(size_t)3 * C_ * C_], g_wql[(size_t)3 * C_ * C_];
__device__ __half g_wph[(size_t)C_ * C_];                             // proj W single
__device__ __half g_qkvh[(size_t)M_ * 3 * C_], g_qkvl[(size_t)M_ * 3 * C_];
__device__ __half g_atth[(size_t)M_ * C_];                            // att single

// ===================== helpers =====================
__device__ __forceinline__ uint32_t smem_u32(const void* p) {
    uint32_t a;
    asm("{ .reg .u64 t; cvta.to.shared.u64 t, %1; cvt.u32.u64 %0, t; }" : "=r"(a) : "l"(p));
    return a;
}
__device__ __forceinline__ void cp_async16(uint32_t saddr, const void* gaddr) {
    asm volatile("cp.async.cg.shared.global [%0], [%1], 16;" :: "r"(saddr), "l"(gaddr));
}
#define CP_COMMIT() asm volatile("cp.async.commit_group;" ::: "memory")
#define CP_WAIT(n)  asm volatile("cp.async.wait_group %0;" :: "n"(n) : "memory")

__device__ __forceinline__ void ldsm4(uint32_t* r, uint32_t a) {
    asm volatile("ldmatrix.sync.aligned.m8n8.x4.shared.b16 {%0,%1,%2,%3}, [%4];"
                 : "=r"(r[0]), "=r"(r[1]), "=r"(r[2]), "=r"(r[3]) : "r"(a));
}
__device__ __forceinline__ void ldsm4t(uint32_t* r, uint32_t a) {
    asm volatile("ldmatrix.sync.aligned.m8n8.x4.trans.shared.b16 {%0,%1,%2,%3}, [%4];"
                 : "=r"(r[0]), "=r"(r[1]), "=r"(r[2]), "=r"(r[3]) : "r"(a));
}
__device__ __forceinline__ void mma_f16(float* d, const uint32_t* a, uint32_t b0, uint32_t b1) {
    asm volatile("mma.sync.aligned.m16n8k16.row.col.f32.f16.f16.f32 "
                 "{%0,%1,%2,%3}, {%4,%5,%6,%7}, {%8,%9}, {%0,%1,%2,%3};"
                 : "+f"(d[0]), "+f"(d[1]), "+f"(d[2]), "+f"(d[3])
                 : "r"(a[0]), "r"(a[1]), "r"(a[2]), "r"(a[3]), "r"(b0), "r"(b1));
}
__device__ __forceinline__ uint32_t packh(float hi, float lo) {
    uint32_t r;
    asm("cvt.rn.f16x2.f32 %0, %1, %2;" : "=r"(r) : "f"(hi), "f"(lo));
    return r;
}
__device__ __forceinline__ float h_lo(uint32_t u) {
    return __half2float(__ushort_as_half((unsigned short)(u & 0xffffu)));
}
__device__ __forceinline__ float h_hi(uint32_t u) {
    return __half2float(__ushort_as_half((unsigned short)(u >> 16)));
}
__device__ __forceinline__ float ex2(float x) {
    float y; asm("ex2.approx.ftz.f32 %0, %1;" : "=f"(y) : "f"(x)); return y;
}

// ===================== split fp32 -> fp16 =====================
__global__ void split1_kernel(const float4* __restrict__ src, uint2* __restrict__ dh, int n4) {
    int i = blockIdx.x * blockDim.x + threadIdx.x;
    if (i >= n4) return;
    float4 v = src[i];
    dh[i] = make_uint2(packh(v.y, v.x), packh(v.w, v.z));
}
__global__ void split2_kernel(const float4* __restrict__ src,
                              uint2* __restrict__ dh, uint2* __restrict__ dl, int n4) {
    int i = blockIdx.x * blockDim.x + threadIdx.x;
    if (i >= n4) return;
    float4 v = src[i];
    uint32_t h0 = packh(v.y, v.x);
    uint32_t h1 = packh(v.w, v.z);
    dh[i] = make_uint2(h0, h1);
    dl[i] = make_uint2(packh(v.y - h_hi(h0), v.x - h_lo(h0)),
                       packh(v.w - h_hi(h1), v.z - h_lo(h1)));
}

// ===================== fp16 GEMM: C = A(MxK) @ B(NxK)^T =====================
// A single fp16; B hi (+lo if HAS_LO). 128x128 CTA tile, BK=32, 3-stage ring.
#define GSTR   80                     // 64 data + 16 pad bytes per 32-col row
#define GTILE  (128 * GSTR)           // 10240
#define EPI_H_STR  272                // fp16 plane stride (128-col rows + pad), bank-clean
#define EPI_H_PLANE (128 * EPI_H_STR) // 34816
#define EPI_F_STR  528                // fp32 plane stride
#define GEMM_SMEM_SPLIT 92160         // 3 stages * 3 tiles (also >= 2*EPI_H_PLANE)
#define GEMM_SMEM_PROJ  67584         // max(3 stages * 2 tiles = 61440, 128*528)

template<bool SPLIT_OUT, bool HAS_LO>
__global__ __launch_bounds__(256, 2) void gemm_f16(
    const __half* __restrict__ Ah,
    const __half* __restrict__ Bh, const __half* __restrict__ Bl,
    float* __restrict__ Cf, __half* __restrict__ Ch, __half* __restrict__ Cl,
    int M, int N, int K) {
    extern __shared__ char smc[];
    const uint32_t sb = smem_u32(smc);
    const int tid = threadIdx.x;
    const int wid = tid >> 5, lane = tid & 31;
    const int g = lane >> 2, t4 = lane & 3;
    const int i8 = lane & 7, mq = lane >> 3;
    const int wm = wid >> 1, wn = wid & 1;
    const int m0 = blockIdx.y * 128, n0 = blockIdx.x * 128;

    constexpr int NMAT = HAS_LO ? 3 : 2;
    constexpr int GSTAGE = NMAT * GTILE;

    auto load_stage = [&](int s, int kt) {
        uint32_t base = sb + s * GSTAGE;
        #pragma unroll
        for (int it = 0; it < 2 * NMAT; it++) {
            int task = it * 256 + tid;                 // 512 tasks per tile
            int mat = task >> 9;                       // 0=A, 1=Bh, 2=Bl
            int rem = task & 511;
            int row = rem >> 2, ch = rem & 3;
            const __half* gp = (mat == 0) ? Ah : (mat == 1) ? Bh : Bl;
            int grow = ((mat == 0) ? m0 : n0) + row;
            cp_async16(base + mat * GTILE + row * GSTR + ch * 16,
                       gp + (size_t)grow * K + kt * 32 + ch * 8);
        }
    };

    float acc[2][8][4];
    #pragma unroll
    for (int mt = 0; mt < 2; mt++)
        #pragma unroll
        for (int nt = 0; nt < 8; nt++)
            #pragma unroll
            for (int i = 0; i < 4; i++) acc[mt][nt][i] = 0.f;

    const int nk = K / 32;            // 32
    load_stage(0, 0); CP_COMMIT();
    load_stage(1, 1); CP_COMMIT();

    const uint32_t aoff = (uint32_t)((wm * 32 + (mq & 1) * 8 + i8) * GSTR + (mq >> 1) * 16);
    const uint32_t boff = (uint32_t)((wn * 64 + (mq >> 1) * 8 + i8) * GSTR + (mq & 1) * 16);

    int s = 0, ls = 2;
    for (int kb = 0; kb < nk; kb++) {
        CP_WAIT(1);
        __syncthreads();

        uint32_t sA  = sb + s * GSTAGE;
        uint32_t sBh = sA + GTILE, sBl = sA + 2 * GTILE;

        #pragma unroll
        for (int kc = 0; kc < 2; kc++) {
            uint32_t a[2][4];
            #pragma unroll
            for (int mt = 0; mt < 2; mt++)
                ldsm4(a[mt], sA + aoff + mt * 16 * GSTR + kc * 32);
            #pragma unroll
            for (int p = 0; p < 4; p++) {
                uint32_t bh4[4];
                ldsm4(bh4, sBh + boff + p * 16 * GSTR + kc * 32);
                uint32_t bl4[4];
                if (HAS_LO) ldsm4(bl4, sBl + boff + p * 16 * GSTR + kc * 32);
                // hi pass (reuse distance 4), then lo pass
                mma_f16(acc[0][2 * p],     a[0], bh4[0], bh4[1]);
                mma_f16(acc[1][2 * p],     a[1], bh4[0], bh4[1]);
                mma_f16(acc[0][2 * p + 1], a[0], bh4[2], bh4[3]);
                mma_f16(acc[1][2 * p + 1], a[1], bh4[2], bh4[3]);
                if (HAS_LO) {
                    mma_f16(acc[0][2 * p],     a[0], bl4[0], bl4[1]);
                    mma_f16(acc[1][2 * p],     a[1], bl4[0], bl4[1]);
                    mma_f16(acc[0][2 * p + 1], a[0], bl4[2], bl4[3]);
                    mma_f16(acc[1][2 * p + 1], a[1], bl4[2], bl4[3]);
                }
            }
        }

        if (kb + 2 < nk) load_stage(ls, kb + 2);
        CP_COMMIT();
        s  = (s  == 2) ? 0 : s + 1;
        ls = (ls == 2) ? 0 : ls + 1;
    }

    // ---- staged epilogue (smem -> coalesced 16B stores) ----
    CP_WAIT(0);
    __syncthreads();          // pipeline smem dead, reuse for staging

    if (SPLIT_OUT) {
        #pragma unroll
        for (int mt = 0; mt < 2; mt++) {
            const int r = wm * 32 + mt * 16 + g;
            #pragma unroll
            for (int nt = 0; nt < 8; nt++) {
                const int c = wn * 64 + nt * 8 + 2 * t4;
                float v0 = acc[mt][nt][0], v1 = acc[mt][nt][1];
                float v2 = acc[mt][nt][2], v3 = acc[mt][nt][3];
                uint32_t uh0 = packh(v1, v0);
                uint32_t ul0 = packh(v1 - h_hi(uh0), v0 - h_lo(uh0));
                uint32_t uh1 = packh(v3, v2);
                uint32_t ul1 = packh(v3 - h_hi(uh1), v2 - h_lo(uh1));
                *(uint32_t*)(smc + r * EPI_H_STR + c * 2)                    = uh0;
                *(uint32_t*)(smc + (r + 8) * EPI_H_STR + c * 2)              = uh1;
                *(uint32_t*)(smc + EPI_H_PLANE + r * EPI_H_STR + c * 2)      = ul0;
                *(uint32_t*)(smc + EPI_H_PLANE + (r + 8) * EPI_H_STR + c * 2) = ul1;
            }
        }
        __syncthreads();
        #pragma unroll
        for (int it = 0; it < 16; it++) {
            int task = it * 256 + tid;        // 4096 tasks
            int plane = task >> 11, rem = task & 2047;
            int row = rem >> 4, ch = rem & 15;
            uint4 v = *(const uint4*)(smc + plane * EPI_H_PLANE + row * EPI_H_STR + ch * 16);
            __half* dst = plane ? Cl : Ch;
            *(uint4*)(dst + (size_t)(m0 + row) * N + n0 + ch * 8) = v;
        }
    } else {
        #pragma unroll
        for (int mt = 0; mt < 2; mt++) {
            const int r = wm * 32 + mt * 16 + g;
            #pragma unroll
            for (int nt = 0; nt < 8; nt++) {
                const int c = wn * 64 + nt * 8 + 2 * t4;
                *(float2*)(smc + r * EPI_F_STR + c * 4) =
                    make_float2(acc[mt][nt][0], acc[mt][nt][1]);
                *(float2*)(smc + (r + 8) * EPI_F_STR + c * 4) =
                    make_float2(acc[mt][nt][2], acc[mt][nt][3]);
            }
        }
        __syncthreads();
        #pragma unroll
        for (int it = 0; it < 16; it++) {
            int task = it * 256 + tid;        // 4096 tasks
            int row = task >> 5, ch = task & 31;
            uint4 v = *(const uint4*)(smc + row * EPI_F_STR + ch * 16);
            *(uint4*)(Cf + (size_t)(m0 + row) * N + n0 + ch * 4) = v;
        }
    }
}

// ===================== flash attention, fp16-2x mma =====================
// Br=128 (8 warps x 16 rows), Bc=64. Q single fp16; K,V hi+lo.
#define ATILE   (64 * 128)              // 8192
#define AQ      (128 * 128)             // 16384 (Q, hi only)
#define ASTAGE  (4 * ATILE)             // 32768 (Kh,Kl,Vh,Vl)
#define ATT_SMEM (AQ + 3 * ASTAGE)      // 114688 -> 2 CTA/SM
#define AEPI_STR 144                    // epilogue plane stride (128B data + 16 pad)

__global__ __launch_bounds__(256, 2) void attn_mma(
    const __half* __restrict__ qkvh, const __half* __restrict__ qkvl,
    __half* __restrict__ oh) {
    extern __shared__ char smc[];
    const uint32_t sb = smem_u32(smc);
    const int tid = threadIdx.x;
    const int w = tid >> 5, lane = tid & 31;
    const int g = lane >> 2, t4 = lane & 3;
    const int i8 = lane & 7, mq = lane >> 3;
    const int qblk = (int)gridDim.x - 1 - (int)blockIdx.x;   // heavy CTAs first
    const int h = blockIdx.y, b = blockIdx.z;
    const int nkt = 2 * qblk + 2;
    const float CS = 0.18033688011112042f;                   // 0.125 * log2(e)
    const float NEGINF = -INFINITY;

    auto load_q = [&]() {
        #pragma unroll
        for (int it = 0; it < 4; it++) {
            int task = it * 256 + tid;       // 0..1023
            int row = task >> 3, ch = task & 7;
            cp_async16(sb + row * 128 + ((ch ^ (row & 7)) * 16),
                       qkvh + ((size_t)(b * T_ + qblk * 128 + row)) * (3 * C_) + h * HD_ + ch * 8);
        }
    };
    auto load_kv = [&](int s, int kt) {
        #pragma unroll
        for (int it = 0; it < 8; it++) {
            int task = it * 256 + tid;       // 0..2047
            int mat = task >> 9;             // 0 Kh, 1 Kl, 2 Vh, 3 Vl
            int rem = task & 511;
            int row = rem >> 3, ch = rem & 7;
            const __half* src = (mat & 1) ? qkvl : qkvh;
            int colbase = ((mat < 2) ? C_ : 2 * C_) + h * HD_;
            cp_async16(sb + AQ + s * ASTAGE + mat * ATILE + row * 128 + ((ch ^ (row & 7)) * 16),
                       src + ((size_t)(b * T_ + kt * 64 + row)) * (3 * C_) + colbase + ch * 8);
        }
    };

    load_q(); load_kv(0, 0); CP_COMMIT();
    load_kv(1, 1); CP_COMMIT();
    CP_WAIT(1);
    __syncthreads();

    uint32_t qh[4][4];
    {
        const uint32_t qrow = (uint32_t)((w * 16 + (mq & 1) * 8 + i8) * 128);
        #pragma unroll
        for (int kc = 0; kc < 4; kc++)
            ldsm4(qh[kc], sb + qrow + ((((mq >> 1) + 2 * kc) ^ i8) * 16));
    }

    float O[8][4];
    #pragma unroll
    for (int nt = 0; nt < 8; nt++)
        #pragma unroll
        for (int i = 0; i < 4; i++) O[nt][i] = 0.f;
    float mcs0 = NEGINF, mcs1 = NEGINF, lsum0 = 0.f, lsum1 = 0.f;
    const int qrow0 = qblk * 128 + w * 16 + g;
    const int qrow1 = qrow0 + 8;

    const uint32_t krow = (uint32_t)(((mq >> 1) * 8 + i8) * 128);
    const uint32_t vrow = (uint32_t)(((mq & 1) * 8 + i8) * 128);

    int st = 0, ls = 2;
    for (int kb = 0; kb < nkt; kb++) {
        if (kb > 0) {
            CP_WAIT(1);
            __syncthreads();
        }
        uint32_t sKH = sb + AQ + st * ASTAGE;
        uint32_t sKL = sKH + ATILE, sVH = sKH + 2 * ATILE, sVL = sKH + 3 * ATILE;

        // ---- S = Q K^T (fp16-2x, hi pass then lo pass per fragment) ----
        float S[8][4];
        #pragma unroll
        for (int nt = 0; nt < 8; nt++)
            #pragma unroll
            for (int i = 0; i < 4; i++) S[nt][i] = 0.f;

        #pragma unroll
        for (int kc = 0; kc < 4; kc++) {
            const uint32_t kcol = (uint32_t)((((mq & 1) + 2 * kc) ^ i8) * 16);
            #pragma unroll
            for (int p = 0; p < 4; p++) {
                uint32_t kh4[4], kl4[4];
                ldsm4(kh4, sKH + krow + p * 16 * 128 + kcol);
                ldsm4(kl4, sKL + krow + p * 16 * 128 + kcol);
                mma_f16(S[2 * p],     qh[kc], kh4[0], kh4[1]);
                mma_f16(S[2 * p + 1], qh[kc], kh4[2], kh4[3]);
                mma_f16(S[2 * p],     qh[kc], kl4[0], kl4[1]);
                mma_f16(S[2 * p + 1], qh[kc], kl4[2], kl4[3]);
            }
        }

        // ---- causal mask ----
        const int kbase = kb * 64;
        if (kbase + 63 > qrow0) {
            #pragma unroll
            for (int nt = 0; nt < 8; nt++) {
                int kc0 = kbase + nt * 8 + 2 * t4;
                if (kc0 > qrow0)     S[nt][0] = NEGINF;
                if (kc0 + 1 > qrow0) S[nt][1] = NEGINF;
                if (kc0 > qrow1)     S[nt][2] = NEGINF;
                if (kc0 + 1 > qrow1) S[nt][3] = NEGINF;
            }
        }

        // ---- online softmax (base-2) ----
        float mx0 = NEGINF, mx1 = NEGINF;
        #pragma unroll
        for (int nt = 0; nt < 8; nt++) {
            mx0 = fmaxf(mx0, fmaxf(S[nt][0], S[nt][1]));
            mx1 = fmaxf(mx1, fmaxf(S[nt][2], S[nt][3]));
        }
        mx0 = fmaxf(mx0, __shfl_xor_sync(0xffffffffu, mx0, 1));
        mx0 = fmaxf(mx0, __shfl_xor_sync(0xffffffffu, mx0, 2));
        mx1 = fmaxf(mx1, __shfl_xor_sync(0xffffffffu, mx1, 1));
        mx1 = fmaxf(mx1, __shfl_xor_sync(0xffffffffu, mx1, 2));
        float mn0 = fmaxf(mcs0, mx0 * CS);
        float mn1 = fmaxf(mcs1, mx1 * CS);
        float a0 = ex2(mcs0 - mn0);
        float a1 = ex2(mcs1 - mn1);
        mcs0 = mn0; mcs1 = mn1;

        float s0 = 0.f, s1 = 0.f;
        #pragma unroll
        for (int nt = 0; nt < 8; nt++) {
            S[nt][0] = ex2(fmaf(S[nt][0], CS, -mcs0)); s0 += S[nt][0];
            S[nt][1] = ex2(fmaf(S[nt][1], CS, -mcs0)); s0 += S[nt][1];
            S[nt][2] = ex2(fmaf(S[nt][2], CS, -mcs1)); s1 += S[nt][2];
            S[nt][3] = ex2(fmaf(S[nt][3], CS, -mcs1)); s1 += S[nt][3];
        }
        s0 += __shfl_xor_sync(0xffffffffu, s0, 1);
        s0 += __shfl_xor_sync(0xffffffffu, s0, 2);
        s1 += __shfl_xor_sync(0xffffffffu, s1, 1);
        s1 += __shfl_xor_sync(0xffffffffu, s1, 2);
        lsum0 = lsum0 * a0 + s0;
        lsum1 = lsum1 * a1 + s1;
        #pragma unroll
        for (int nt = 0; nt < 8; nt++) {
            O[nt][0] *= a0; O[nt][1] *= a0;
            O[nt][2] *= a1; O[nt][3] *= a1;
        }

        // ---- P (fp16 a-frags) then O += P V (hi pass / lo pass) ----
        #pragma unroll
        for (int j = 0; j < 4; j++) {
            uint32_t ph[4];
            ph[0] = packh(S[2 * j][1],     S[2 * j][0]);
            ph[1] = packh(S[2 * j][3],     S[2 * j][2]);
            ph[2] = packh(S[2 * j + 1][1], S[2 * j + 1][0]);
            ph[3] = packh(S[2 * j + 1][3], S[2 * j + 1][2]);
            #pragma unroll
            for (int p = 0; p < 4; p++) {
                const uint32_t vcol = (uint32_t)((((mq >> 1) + 2 * p) ^ i8) * 16);
                uint32_t vh4[4], vl4[4];
                ldsm4t(vh4, sVH + vrow + j * 16 * 128 + vcol);
                ldsm4t(vl4, sVL + vrow + j * 16 * 128 + vcol);
                mma_f16(O[2 * p],     ph, vh4[0], vh4[1]);
                mma_f16(O[2 * p + 1], ph, vh4[2], vh4[3]);
                mma_f16(O[2 * p],     ph, vl4[0], vl4[1]);
                mma_f16(O[2 * p + 1], ph, vl4[2], vl4[3]);
            }
        }

        if (kb + 2 < nkt) load_kv(ls, kb + 2);
        CP_COMMIT();
        st = (st == 2) ? 0 : st + 1;
        ls = (ls == 2) ? 0 : ls + 1;
    }

    // ---- staged epilogue ----
    const float rl0 = 1.0f / lsum0, rl1 = 1.0f / lsum1;
    __syncthreads();                     // all warps done computing; smem reusable
    {
        const int r = w * 16 + g;
        #pragma unroll
        for (int nt = 0; nt < 8; nt++) {
            const int c = nt * 8 + 2 * t4;
            *(uint32_t*)(smc + r * AEPI_STR + c * 2) =
                packh(O[nt][1] * rl0, O[nt][0] * rl0);
            *(uint32_t*)(smc + (r + 8) * AEPI_STR + c * 2) =
                packh(O[nt][3] * rl1, O[nt][2] * rl1);
        }
    }
    __syncthreads();
    #pragma unroll
    for (int it = 0; it < 4; it++) {
        int task = it * 256 + tid;       // 1024 tasks
        int row = task >> 3, ch = task & 7;
        uint4 v = *(const uint4*)(smc + row * AEPI_STR + ch * 16);
        *(uint4*)(oh + ((size_t)(b * T_ + qblk * 128 + row)) * C_ + h * HD_ + ch * 8) = v;
    }
}

// ===================== launch =====================
extern "C" void kernel_launch(void* const* d_in, const int* in_sizes, int n_in,
                              void* d_out, int out_size) {
    (void)in_sizes; (void)n_in; (void)out_size;
    const float* x      = (const float*)d_in[0];
    const float* w_qkv  = (const float*)d_in[1];
    const float* w_proj = (const float*)d_in[2];
    float* out = (float*)d_out;

    __half *xh, *wqh, *wql, *wph, *qkvh, *qkvl, *atth;
    cudaGetSymbolAddress((void**)&xh, g_xh);
    cudaGetSymbolAddress((void**)&wqh, g_wqh);   cudaGetSymbolAddress((void**)&wql, g_wql);
    cudaGetSymbolAddress((void**)&wph, g_wph);
    cudaGetSymbolAddress((void**)&qkvh, g_qkvh); cudaGetSymbolAddress((void**)&qkvl, g_qkvl);
    cudaGetSymbolAddress((void**)&atth, g_atth);

    cudaFuncSetAttribute((const void*)gemm_f16<true, true>,
                         cudaFuncAttributeMaxDynamicSharedMemorySize, GEMM_SMEM_SPLIT);
    cudaFuncSetAttribute((const void*)gemm_f16<false, false>,
                         cudaFuncAttributeMaxDynamicSharedMemorySize, GEMM_SMEM_PROJ);
    cudaFuncSetAttribute((const void*)attn_mma,
                         cudaFuncAttributeMaxDynamicSharedMemorySize, ATT_SMEM);

    // 0) split inputs
    {
        int n4;
        n4 = M_ * C_ / 4;
        split1_kernel<<<(n4 + 255) / 256, 256>>>((const float4*)x, (uint2*)xh, n4);
        n4 = 3 * C_ * C_ / 4;
        split2_kernel<<<(n4 + 255) / 256, 256>>>((const float4*)w_qkv, (uint2*)wqh, (uint2*)wql, n4);
        n4 = C_ * C_ / 4;
        split1_kernel<<<(n4 + 255) / 256, 256>>>((const float4*)w_proj, (uint2*)wph, n4);
    }

    // 1) qkv = x @ w_qkv^T  -> hi/lo fp16
    gemm_f16<true, true><<<dim3(3 * C_ / 128, M_ / 128), 256, GEMM_SMEM_SPLIT>>>(
        xh, wqh, wql, nullptr, qkvh, qkvl, M_, 3 * C_, C_);

    // 2) attention -> fp16 (single)
    attn_mma<<<dim3(T_ / 128, H_, B_), 256, ATT_SMEM>>>(qkvh, qkvl, atth);

    // 3) out = att @ w_proj^T  (fp32 out, W single fp16)
    gemm_f16<false, false><<<dim3(C_ / 128, M_ / 128), 256, GEMM_SMEM_PROJ>>>(
        atth, wph, nullptr, out, nullptr, nullptr, M_, C_, C_);
}

// round 8
// speedup vs baseline: 6.1510x; 1.2578x over previous
#include <cuda_runtime.h>
#include <cuda_fp16.h>
#include <math.h>
#include <stdint.h>

#define T_   2048
#define H_   16
#define HD_  64
#define C_   1024
#define B_   2
#define M_   (B_ * T_)          // 4096

// ===================== device scratch (fp16) =====================
__device__ __half g_xh[(size_t)M_ * C_];                              // x single
__device__ __half g_wqh[(size_t)3 * C_ * C_], g_wql[(size_t)3 * C_ * C_];
__device__ __half g_wph[(size_t)C_ * C_];                             // proj W single
__device__ __half g_qkvh[(size_t)M_ * 3 * C_];                        // qkv single
__device__ __half g_atth[(size_t)M_ * C_];                            // att single

// ===================== helpers =====================
__device__ __forceinline__ uint32_t smem_u32(const void* p) {
    uint32_t a;
    asm("{ .reg .u64 t; cvta.to.shared.u64 t, %1; cvt.u32.u64 %0, t; }" : "=r"(a) : "l"(p));
    return a;
}
__device__ __forceinline__ void cp_async16(uint32_t saddr, const void* gaddr) {
    asm volatile("cp.async.cg.shared.global [%0], [%1], 16;" :: "r"(saddr), "l"(gaddr));
}
#define CP_COMMIT() asm volatile("cp.async.commit_group;" ::: "memory")
#define CP_WAIT(n)  asm volatile("cp.async.wait_group %0;" :: "n"(n) : "memory")

__device__ __forceinline__ void ldsm4(uint32_t* r, uint32_t a) {
    asm volatile("ldmatrix.sync.aligned.m8n8.x4.shared.b16 {%0,%1,%2,%3}, [%4];"
                 : "=r"(r[0]), "=r"(r[1]), "=r"(r[2]), "=r"(r[3]) : "r"(a));
}
__device__ __forceinline__ void ldsm4t(uint32_t* r, uint32_t a) {
    asm volatile("ldmatrix.sync.aligned.m8n8.x4.trans.shared.b16 {%0,%1,%2,%3}, [%4];"
                 : "=r"(r[0]), "=r"(r[1]), "=r"(r[2]), "=r"(r[3]) : "r"(a));
}
__device__ __forceinline__ void mma_f16(float* d, const uint32_t* a, uint32_t b0, uint32_t b1) {
    asm volatile("mma.sync.aligned.m16n8k16.row.col.f32.f16.f16.f32 "
                 "{%0,%1,%2,%3}, {%4,%5,%6,%7}, {%8,%9}, {%0,%1,%2,%3};"
                 : "+f"(d[0]), "+f"(d[1]), "+f"(d[2]), "+f"(d[3])
                 : "r"(a[0]), "r"(a[1]), "r"(a[2]), "r"(a[3]), "r"(b0), "r"(b1));
}
__device__ __forceinline__ uint32_t packh(float hi, float lo) {
    uint32_t r;
    asm("cvt.rn.f16x2.f32 %0, %1, %2;" : "=r"(r) : "f"(hi), "f"(lo));
    return r;
}
__device__ __forceinline__ float h_lo(uint32_t u) {
    return __half2float(__ushort_as_half((unsigned short)(u & 0xffffu)));
}
__device__ __forceinline__ float h_hi(uint32_t u) {
    return __half2float(__ushort_as_half((unsigned short)(u >> 16)));
}
__device__ __forceinline__ float ex2(float x) {
    float y; asm("ex2.approx.ftz.f32 %0, %1;" : "=f"(y) : "f"(x)); return y;
}

// ===================== fused split fp32 -> fp16 =====================
// region 0: x -> xh (single); region 1: w_qkv -> wqh+wql; region 2: w_proj -> wph
#define N4_X   (M_ * C_ / 4)
#define N4_WQ  (3 * C_ * C_ / 4)
#define N4_WP  (C_ * C_ / 4)

__global__ void split_all(const float4* __restrict__ x, const float4* __restrict__ wq,
                          const float4* __restrict__ wp,
                          uint2* __restrict__ xh,
                          uint2* __restrict__ wqh, uint2* __restrict__ wql,
                          uint2* __restrict__ wph) {
    int i = blockIdx.x * blockDim.x + threadIdx.x;
    if (i < N4_X) {
        float4 v = x[i];
        xh[i] = make_uint2(packh(v.y, v.x), packh(v.w, v.z));
    } else if (i < N4_X + N4_WQ) {
        int j = i - N4_X;
        float4 v = wq[j];
        uint32_t h0 = packh(v.y, v.x);
        uint32_t h1 = packh(v.w, v.z);
        wqh[j] = make_uint2(h0, h1);
        wql[j] = make_uint2(packh(v.y - h_hi(h0), v.x - h_lo(h0)),
                            packh(v.w - h_hi(h1), v.z - h_lo(h1)));
    } else if (i < N4_X + N4_WQ + N4_WP) {
        int j = i - N4_X - N4_WQ;
        float4 v = wp[j];
        wph[j] = make_uint2(packh(v.y, v.x), packh(v.w, v.z));
    }
}

// ===================== fp16 GEMM: C = A(MxK) @ B(NxK)^T =====================
// A single fp16; B hi (+lo if HAS_LO). 128x128 CTA tile, BK=32, 3-stage ring.
#define GSTR   80                     // 64 data + 16 pad bytes per 32-col row
#define GTILE  (128 * GSTR)           // 10240
#define EPI_H_STR  272                // fp16 staging stride (256B data + 16 pad)
#define EPI_F_STR  528                // fp32 staging stride
#define GEMM_SMEM_SPLIT 92160         // 3 stages * 3 tiles
#define GEMM_SMEM_PROJ  67584         // max(3 stages * 2 tiles, 128*528)

template<bool HALF_OUT, bool HAS_LO>
__global__ __launch_bounds__(256, 2) void gemm_f16(
    const __half* __restrict__ Ah,
    const __half* __restrict__ Bh, const __half* __restrict__ Bl,
    float* __restrict__ Cf, __half* __restrict__ Ch,
    int M, int N, int K) {
    extern __shared__ char smc[];
    const uint32_t sb = smem_u32(smc);
    const int tid = threadIdx.x;
    const int wid = tid >> 5, lane = tid & 31;
    const int g = lane >> 2, t4 = lane & 3;
    const int i8 = lane & 7, mq = lane >> 3;
    const int wm = wid >> 1, wn = wid & 1;
    const int m0 = blockIdx.y * 128, n0 = blockIdx.x * 128;

    constexpr int NMAT = HAS_LO ? 3 : 2;
    constexpr int GSTAGE = NMAT * GTILE;

    auto load_stage = [&](int s, int kt) {
        uint32_t base = sb + s * GSTAGE;
        #pragma unroll
        for (int it = 0; it < 2 * NMAT; it++) {
            int task = it * 256 + tid;                 // 512 tasks per tile
            int mat = task >> 9;                       // 0=A, 1=Bh, 2=Bl
            int rem = task & 511;
            int row = rem >> 2, ch = rem & 3;
            const __half* gp = (mat == 0) ? Ah : (mat == 1) ? Bh : Bl;
            int grow = ((mat == 0) ? m0 : n0) + row;
            cp_async16(base + mat * GTILE + row * GSTR + ch * 16,
                       gp + (size_t)grow * K + kt * 32 + ch * 8);
        }
    };

    float acc[2][8][4];
    #pragma unroll
    for (int mt = 0; mt < 2; mt++)
        #pragma unroll
        for (int nt = 0; nt < 8; nt++)
            #pragma unroll
            for (int i = 0; i < 4; i++) acc[mt][nt][i] = 0.f;

    const int nk = K / 32;            // 32
    load_stage(0, 0); CP_COMMIT();
    load_stage(1, 1); CP_COMMIT();

    const uint32_t aoff = (uint32_t)((wm * 32 + (mq & 1) * 8 + i8) * GSTR + (mq >> 1) * 16);
    const uint32_t boff = (uint32_t)((wn * 64 + (mq >> 1) * 8 + i8) * GSTR + (mq & 1) * 16);

    int s = 0, ls = 2;
    for (int kb = 0; kb < nk; kb++) {
        CP_WAIT(1);
        __syncthreads();

        uint32_t sA  = sb + s * GSTAGE;
        uint32_t sBh = sA + GTILE, sBl = sA + 2 * GTILE;

        #pragma unroll
        for (int kc = 0; kc < 2; kc++) {
            uint32_t a[2][4];
            #pragma unroll
            for (int mt = 0; mt < 2; mt++)
                ldsm4(a[mt], sA + aoff + mt * 16 * GSTR + kc * 32);
            #pragma unroll
            for (int p = 0; p < 4; p++) {
                uint32_t bh4[4];
                ldsm4(bh4, sBh + boff + p * 16 * GSTR + kc * 32);
                uint32_t bl4[4];
                if (HAS_LO) ldsm4(bl4, sBl + boff + p * 16 * GSTR + kc * 32);
                mma_f16(acc[0][2 * p],     a[0], bh4[0], bh4[1]);
                mma_f16(acc[1][2 * p],     a[1], bh4[0], bh4[1]);
                mma_f16(acc[0][2 * p + 1], a[0], bh4[2], bh4[3]);
                mma_f16(acc[1][2 * p + 1], a[1], bh4[2], bh4[3]);
                if (HAS_LO) {
                    mma_f16(acc[0][2 * p],     a[0], bl4[0], bl4[1]);
                    mma_f16(acc[1][2 * p],     a[1], bl4[0], bl4[1]);
                    mma_f16(acc[0][2 * p + 1], a[0], bl4[2], bl4[3]);
                    mma_f16(acc[1][2 * p + 1], a[1], bl4[2], bl4[3]);
                }
            }
        }

        if (kb + 2 < nk) load_stage(ls, kb + 2);
        CP_COMMIT();
        s  = (s  == 2) ? 0 : s + 1;
        ls = (ls == 2) ? 0 : ls + 1;
    }

    // ---- staged epilogue (smem -> coalesced 16B stores) ----
    CP_WAIT(0);
    __syncthreads();

    if (HALF_OUT) {
        #pragma unroll
        for (int mt = 0; mt < 2; mt++) {
            const int r = wm * 32 + mt * 16 + g;
            #pragma unroll
            for (int nt = 0; nt < 8; nt++) {
                const int c = wn * 64 + nt * 8 + 2 * t4;
                *(uint32_t*)(smc + r * EPI_H_STR + c * 2) =
                    packh(acc[mt][nt][1], acc[mt][nt][0]);
                *(uint32_t*)(smc + (r + 8) * EPI_H_STR + c * 2) =
                    packh(acc[mt][nt][3], acc[mt][nt][2]);
            }
        }
        __syncthreads();
        #pragma unroll
        for (int it = 0; it < 8; it++) {
            int task = it * 256 + tid;        // 2048 tasks: 128 rows x 16 chunks
            int row = task >> 4, ch = task & 15;
            uint4 v = *(const uint4*)(smc + row * EPI_H_STR + ch * 16);
            *(uint4*)(Ch + (size_t)(m0 + row) * N + n0 + ch * 8) = v;
        }
    } else {
        #pragma unroll
        for (int mt = 0; mt < 2; mt++) {
            const int r = wm * 32 + mt * 16 + g;
            #pragma unroll
            for (int nt = 0; nt < 8; nt++) {
                const int c = wn * 64 + nt * 8 + 2 * t4;
                *(float2*)(smc + r * EPI_F_STR + c * 4) =
                    make_float2(acc[mt][nt][0], acc[mt][nt][1]);
                *(float2*)(smc + (r + 8) * EPI_F_STR + c * 4) =
                    make_float2(acc[mt][nt][2], acc[mt][nt][3]);
            }
        }
        __syncthreads();
        #pragma unroll
        for (int it = 0; it < 16; it++) {
            int task = it * 256 + tid;        // 4096 tasks
            int row = task >> 5, ch = task & 31;
            uint4 v = *(const uint4*)(smc + row * EPI_F_STR + ch * 16);
            *(uint4*)(Cf + (size_t)(m0 + row) * N + n0 + ch * 4) = v;
        }
    }
}

// ===================== flash attention, single-fp16 K/V =====================
// Br=128 (8 warps x 16 rows), Bc=64. Q, K, V single fp16; 4-stage KV ring.
#define ATILE   (64 * 128)              // 8192
#define AQ      (128 * 128)             // 16384
#define ASTAGE  (2 * ATILE)             // 16384 (Kh, Vh)
#define ATT_SMEM (AQ + 4 * ASTAGE)      // 81920 -> 2 CTA/SM
#define AEPI_STR 144

__global__ __launch_bounds__(256, 2) void attn_mma(
    const __half* __restrict__ qkvh, __half* __restrict__ oh) {
    extern __shared__ char smc[];
    const uint32_t sb = smem_u32(smc);
    const int tid = threadIdx.x;
    const int w = tid >> 5, lane = tid & 31;
    const int g = lane >> 2, t4 = lane & 3;
    const int i8 = lane & 7, mq = lane >> 3;
    const int qblk = (int)gridDim.x - 1 - (int)blockIdx.x;   // heavy CTAs first
    const int h = blockIdx.y, b = blockIdx.z;
    const int nkt = 2 * qblk + 2;
    const float CS = 0.18033688011112042f;                   // 0.125 * log2(e)
    const float NEGINF = -INFINITY;

    auto load_q = [&]() {
        #pragma unroll
        for (int it = 0; it < 4; it++) {
            int task = it * 256 + tid;       // 0..1023
            int row = task >> 3, ch = task & 7;
            cp_async16(sb + row * 128 + ((ch ^ (row & 7)) * 16),
                       qkvh + ((size_t)(b * T_ + qblk * 128 + row)) * (3 * C_) + h * HD_ + ch * 8);
        }
    };
    auto load_kv = [&](int s, int kt) {
        #pragma unroll
        for (int it = 0; it < 4; it++) {
            int task = it * 256 + tid;       // 0..1023
            int mat = task >> 9;             // 0 K, 1 V
            int rem = task & 511;
            int row = rem >> 3, ch = rem & 7;
            int colbase = ((mat == 0) ? C_ : 2 * C_) + h * HD_;
            cp_async16(sb + AQ + s * ASTAGE + mat * ATILE + row * 128 + ((ch ^ (row & 7)) * 16),
                       qkvh + ((size_t)(b * T_ + kt * 64 + row)) * (3 * C_) + colbase + ch * 8);
        }
    };

    load_q(); load_kv(0, 0); CP_COMMIT();
    load_kv(1, 1); CP_COMMIT();
    if (nkt > 2) load_kv(2, 2);
    CP_COMMIT();
    CP_WAIT(2);
    __syncthreads();

    uint32_t qh[4][4];
    {
        const uint32_t qrow = (uint32_t)((w * 16 + (mq & 1) * 8 + i8) * 128);
        #pragma unroll
        for (int kc = 0; kc < 4; kc++)
            ldsm4(qh[kc], sb + qrow + ((((mq >> 1) + 2 * kc) ^ i8) * 16));
    }

    float O[8][4];
    #pragma unroll
    for (int nt = 0; nt < 8; nt++)
        #pragma unroll
        for (int i = 0; i < 4; i++) O[nt][i] = 0.f;
    float mcs0 = NEGINF, mcs1 = NEGINF, lsum0 = 0.f, lsum1 = 0.f;
    const int qrow0 = qblk * 128 + w * 16 + g;
    const int qrow1 = qrow0 + 8;

    const uint32_t krow = (uint32_t)(((mq >> 1) * 8 + i8) * 128);
    const uint32_t vrow = (uint32_t)(((mq & 1) * 8 + i8) * 128);

    int st = 0, ls = 3;
    for (int kb = 0; kb < nkt; kb++) {
        if (kb > 0) {
            CP_WAIT(2);
            __syncthreads();
        }
        uint32_t sKH = sb + AQ + st * ASTAGE;
        uint32_t sVH = sKH + ATILE;

        // ---- S = Q K^T ----
        float S[8][4];
        #pragma unroll
        for (int nt = 0; nt < 8; nt++)
            #pragma unroll
            for (int i = 0; i < 4; i++) S[nt][i] = 0.f;

        #pragma unroll
        for (int kc = 0; kc < 4; kc++) {
            const uint32_t kcol = (uint32_t)((((mq & 1) + 2 * kc) ^ i8) * 16);
            #pragma unroll
            for (int p = 0; p < 4; p++) {
                uint32_t kh4[4];
                ldsm4(kh4, sKH + krow + p * 16 * 128 + kcol);
                mma_f16(S[2 * p],     qh[kc], kh4[0], kh4[1]);
                mma_f16(S[2 * p + 1], qh[kc], kh4[2], kh4[3]);
            }
        }

        // ---- causal mask ----
        const int kbase = kb * 64;
        if (kbase + 63 > qrow0) {
            #pragma unroll
            for (int nt = 0; nt < 8; nt++) {
                int kc0 = kbase + nt * 8 + 2 * t4;
                if (kc0 > qrow0)     S[nt][0] = NEGINF;
                if (kc0 + 1 > qrow0) S[nt][1] = NEGINF;
                if (kc0 > qrow1)     S[nt][2] = NEGINF;
                if (kc0 + 1 > qrow1) S[nt][3] = NEGINF;
            }
        }

        // ---- online softmax (base-2) ----
        float mx0 = NEGINF, mx1 = NEGINF;
        #pragma unroll
        for (int nt = 0; nt < 8; nt++) {
            mx0 = fmaxf(mx0, fmaxf(S[nt][0], S[nt][1]));
            mx1 = fmaxf(mx1, fmaxf(S[nt][2], S[nt][3]));
        }
        mx0 = fmaxf(mx0, __shfl_xor_sync(0xffffffffu, mx0, 1));
        mx0 = fmaxf(mx0, __shfl_xor_sync(0xffffffffu, mx0, 2));
        mx1 = fmaxf(mx1, __shfl_xor_sync(0xffffffffu, mx1, 1));
        mx1 = fmaxf(mx1, __shfl_xor_sync(0xffffffffu, mx1, 2));
        float mn0 = fmaxf(mcs0, mx0 * CS);
        float mn1 = fmaxf(mcs1, mx1 * CS);
        float a0 = ex2(mcs0 - mn0);
        float a1 = ex2(mcs1 - mn1);
        mcs0 = mn0; mcs1 = mn1;

        float s0 = 0.f, s1 = 0.f;
        #pragma unroll
        for (int nt = 0; nt < 8; nt++) {
            S[nt][0] = ex2(fmaf(S[nt][0], CS, -mcs0)); s0 += S[nt][0];
            S[nt][1] = ex2(fmaf(S[nt][1], CS, -mcs0)); s0 += S[nt][1];
            S[nt][2] = ex2(fmaf(S[nt][2], CS, -mcs1)); s1 += S[nt][2];
            S[nt][3] = ex2(fmaf(S[nt][3], CS, -mcs1)); s1 += S[nt][3];
        }
        s0 += __shfl_xor_sync(0xffffffffu, s0, 1);
        s0 += __shfl_xor_sync(0xffffffffu, s0, 2);
        s1 += __shfl_xor_sync(0xffffffffu, s1, 1);
        s1 += __shfl_xor_sync(0xffffffffu, s1, 2);
        lsum0 = lsum0 * a0 + s0;
        lsum1 = lsum1 * a1 + s1;
        #pragma unroll
        for (int nt = 0; nt < 8; nt++) {
            O[nt][0] *= a0; O[nt][1] *= a0;
            O[nt][2] *= a1; O[nt][3] *= a1;
        }

        // ---- P (fp16 a-frags) then O += P V ----
        #pragma unroll
        for (int j = 0; j < 4; j++) {
            uint32_t ph[4];
            ph[0] = packh(S[2 * j][1],     S[2 * j][0]);
            ph[1] = packh(S[2 * j][3],     S[2 * j][2]);
            ph[2] = packh(S[2 * j + 1][1], S[2 * j + 1][0]);
            ph[3] = packh(S[2 * j + 1][3], S[2 * j + 1][2]);
            #pragma unroll
            for (int p = 0; p < 4; p++) {
                const uint32_t vcol = (uint32_t)((((mq >> 1) + 2 * p) ^ i8) * 16);
                uint32_t vh4[4];
                ldsm4t(vh4, sVH + vrow + j * 16 * 128 + vcol);
                mma_f16(O[2 * p],     ph, vh4[0], vh4[1]);
                mma_f16(O[2 * p + 1], ph, vh4[2], vh4[3]);
            }
        }

        if (kb + 3 < nkt) load_kv(ls, kb + 3);
        CP_COMMIT();
        st = (st + 1) & 3;
        ls = (ls + 1) & 3;
    }

    // ---- staged epilogue ----
    const float rl0 = 1.0f / lsum0, rl1 = 1.0f / lsum1;
    __syncthreads();
    {
        const int r = w * 16 + g;
        #pragma unroll
        for (int nt = 0; nt < 8; nt++) {
            const int c = nt * 8 + 2 * t4;
            *(uint32_t*)(smc + r * AEPI_STR + c * 2) =
                packh(O[nt][1] * rl0, O[nt][0] * rl0);
            *(uint32_t*)(smc + (r + 8) * AEPI_STR + c * 2) =
                packh(O[nt][3] * rl1, O[nt][2] * rl1);
        }
    }
    __syncthreads();
    #pragma unroll
    for (int it = 0; it < 4; it++) {
        int task = it * 256 + tid;       // 1024 tasks
        int row = task >> 3, ch = task & 7;
        uint4 v = *(const uint4*)(smc + row * AEPI_STR + ch * 16);
        *(uint4*)(oh + ((size_t)(b * T_ + qblk * 128 + row)) * C_ + h * HD_ + ch * 8) = v;
    }
}

// ===================== launch =====================
extern "C" void kernel_launch(void* const* d_in, const int* in_sizes, int n_in,
                              void* d_out, int out_size) {
    (void)in_sizes; (void)n_in; (void)out_size;
    const float* x      = (const float*)d_in[0];
    const float* w_qkv  = (const float*)d_in[1];
    const float* w_proj = (const float*)d_in[2];
    float* out = (float*)d_out;

    __half *xh, *wqh, *wql, *wph, *qkvh, *atth;
    cudaGetSymbolAddress((void**)&xh, g_xh);
    cudaGetSymbolAddress((void**)&wqh, g_wqh);   cudaGetSymbolAddress((void**)&wql, g_wql);
    cudaGetSymbolAddress((void**)&wph, g_wph);
    cudaGetSymbolAddress((void**)&qkvh, g_qkvh);
    cudaGetSymbolAddress((void**)&atth, g_atth);

    cudaFuncSetAttribute((const void*)gemm_f16<true, true>,
                         cudaFuncAttributeMaxDynamicSharedMemorySize, GEMM_SMEM_SPLIT);
    cudaFuncSetAttribute((const void*)gemm_f16<false, false>,
                         cudaFuncAttributeMaxDynamicSharedMemorySize, GEMM_SMEM_PROJ);
    cudaFuncSetAttribute((const void*)attn_mma,
                         cudaFuncAttributeMaxDynamicSharedMemorySize, ATT_SMEM);

    // 0) fused input split
    {
        int total = N4_X + N4_WQ + N4_WP;
        split_all<<<(total + 255) / 256, 256>>>(
            (const float4*)x, (const float4*)w_qkv, (const float4*)w_proj,
            (uint2*)xh, (uint2*)wqh, (uint2*)wql, (uint2*)wph);
    }

    // 1) qkv = x @ w_qkv^T  -> fp16 (W hi/lo 2-pass for accuracy)
    gemm_f16<true, true><<<dim3(3 * C_ / 128, M_ / 128), 256, GEMM_SMEM_SPLIT>>>(
        xh, wqh, wql, nullptr, qkvh, M_, 3 * C_, C_);

    // 2) attention -> fp16
    attn_mma<<<dim3(T_ / 128, H_, B_), 256, ATT_SMEM>>>(qkvh, atth);

    // 3) out = att @ w_proj^T  (fp32 out, W single fp16)
    gemm_f16<false, false><<<dim3(C_ / 128, M_ / 128), 256, GEMM_SMEM_PROJ>>>(
        atth, wph, nullptr, out, nullptr, M_, C_, C_);
}

// round 10
// speedup vs baseline: 7.7674x; 1.2628x over previous
#include <cuda_runtime.h>
#include <cuda_fp16.h>
#include <math.h>
#include <stdint.h>

#define T_   2048
#define H_   16
#define HD_  64
#define C_   1024
#define B_   2
#define M_   (B_ * T_)          // 4096

// ===================== device scratch (fp16, all single) =====================
__device__ __half g_xh[(size_t)M_ * C_];
__device__ __half g_wqh[(size_t)3 * C_ * C_];
__device__ __half g_wph[(size_t)C_ * C_];
__device__ __half g_qkvh[(size_t)M_ * 3 * C_];
__device__ __half g_atth[(size_t)M_ * C_];

// ===================== helpers =====================
__device__ __forceinline__ uint32_t smem_u32(const void* p) {
    uint32_t a;
    asm("{ .reg .u64 t; cvta.to.shared.u64 t, %1; cvt.u32.u64 %0, t; }" : "=r"(a) : "l"(p));
    return a;
}
__device__ __forceinline__ void cp_async16(uint32_t saddr, const void* gaddr) {
    asm volatile("cp.async.cg.shared.global [%0], [%1], 16;" :: "r"(saddr), "l"(gaddr));
}
#define CP_COMMIT() asm volatile("cp.async.commit_group;" ::: "memory")
#define CP_WAIT(n)  asm volatile("cp.async.wait_group %0;" :: "n"(n) : "memory")

__device__ __forceinline__ void ldsm4(uint32_t* r, uint32_t a) {
    asm volatile("ldmatrix.sync.aligned.m8n8.x4.shared.b16 {%0,%1,%2,%3}, [%4];"
                 : "=r"(r[0]), "=r"(r[1]), "=r"(r[2]), "=r"(r[3]) : "r"(a));
}
__device__ __forceinline__ void ldsm4t(uint32_t* r, uint32_t a) {
    asm volatile("ldmatrix.sync.aligned.m8n8.x4.trans.shared.b16 {%0,%1,%2,%3}, [%4];"
                 : "=r"(r[0]), "=r"(r[1]), "=r"(r[2]), "=r"(r[3]) : "r"(a));
}
__device__ __forceinline__ void mma_f16(float* d, const uint32_t* a, uint32_t b0, uint32_t b1) {
    asm volatile("mma.sync.aligned.m16n8k16.row.col.f32.f16.f16.f32 "
                 "{%0,%1,%2,%3}, {%4,%5,%6,%7}, {%8,%9}, {%0,%1,%2,%3};"
                 : "+f"(d[0]), "+f"(d[1]), "+f"(d[2]), "+f"(d[3])
                 : "r"(a[0]), "r"(a[1]), "r"(a[2]), "r"(a[3]), "r"(b0), "r"(b1));
}
__device__ __forceinline__ uint32_t packh(float hi, float lo) {
    uint32_t r;
    asm("cvt.rn.f16x2.f32 %0, %1, %2;" : "=r"(r) : "f"(hi), "f"(lo));
    return r;
}
__device__ __forceinline__ float ex2(float x) {
    float y; asm("ex2.approx.ftz.f32 %0, %1;" : "=f"(y) : "f"(x)); return y;
}

// ===================== fused split fp32 -> fp16 (all single) =====================
#define N4_X   (M_ * C_ / 4)
#define N4_WQ  (3 * C_ * C_ / 4)
#define N4_WP  (C_ * C_ / 4)

__global__ void split_all(const float4* __restrict__ x, const float4* __restrict__ wq,
                          const float4* __restrict__ wp,
                          uint2* __restrict__ xh, uint2* __restrict__ wqh,
                          uint2* __restrict__ wph) {
    int i = blockIdx.x * blockDim.x + threadIdx.x;
    const float4* src;
    uint2* dst;
    int j;
    if (i < N4_X)                     { src = x;  dst = xh;  j = i; }
    else if (i < N4_X + N4_WQ)        { src = wq; dst = wqh; j = i - N4_X; }
    else if (i < N4_X + N4_WQ + N4_WP){ src = wp; dst = wph; j = i - N4_X - N4_WQ; }
    else return;
    float4 v = src[j];
    dst[j] = make_uint2(packh(v.y, v.x), packh(v.w, v.z));
}

// ===================== fp16 GEMM: C = A(MxK) @ B(NxK)^T =====================
// All single fp16. 128x128 CTA tile, BK=32, 4-stage cp.async ring.
#define GSTR   80                     // 64 data + 16 pad bytes per 32-col row
#define GTILE  (128 * GSTR)           // 10240
#define GSTAGE (2 * GTILE)            // 20480 (A, B)
#define EPI_H_STR  272
#define EPI_F_STR  528
#define GEMM_SMEM  81920              // max(4 stages * 20480, epilogue staging)

template<bool HALF_OUT>
__global__ __launch_bounds__(256, 2) void gemm_f16(
    const __half* __restrict__ Ah, const __half* __restrict__ Bh,
    float* __restrict__ Cf, __half* __restrict__ Ch,
    int M, int N, int K) {
    extern __shared__ char smc[];
    const uint32_t sb = smem_u32(smc);
    const int tid = threadIdx.x;
    const int wid = tid >> 5, lane = tid & 31;
    const int g = lane >> 2, t4 = lane & 3;
    const int i8 = lane & 7, mq = lane >> 3;
    const int wm = wid >> 1, wn = wid & 1;
    const int m0 = blockIdx.y * 128, n0 = blockIdx.x * 128;

    auto load_stage = [&](int s, int kt) {
        uint32_t base = sb + s * GSTAGE;
        #pragma unroll
        for (int it = 0; it < 4; it++) {
            int task = it * 256 + tid;                 // 1024 tasks
            int mat = task >> 9;                       // 0=A, 1=B
            int rem = task & 511;
            int row = rem >> 2, ch = rem & 3;
            const __half* gp = (mat == 0) ? Ah : Bh;
            int grow = ((mat == 0) ? m0 : n0) + row;
            cp_async16(base + mat * GTILE + row * GSTR + ch * 16,
                       gp + (size_t)grow * K + kt * 32 + ch * 8);
        }
    };

    float acc[2][8][4];
    #pragma unroll
    for (int mt = 0; mt < 2; mt++)
        #pragma unroll
        for (int nt = 0; nt < 8; nt++)
            #pragma unroll
            for (int i = 0; i < 4; i++) acc[mt][nt][i] = 0.f;

    const int nk = K / 32;            // 32
    load_stage(0, 0); CP_COMMIT();
    load_stage(1, 1); CP_COMMIT();
    load_stage(2, 2); CP_COMMIT();

    const uint32_t aoff = (uint32_t)((wm * 32 + (mq & 1) * 8 + i8) * GSTR + (mq >> 1) * 16);
    const uint32_t boff = (uint32_t)((wn * 64 + (mq >> 1) * 8 + i8) * GSTR + (mq & 1) * 16);

    int s = 0, ls = 3;
    for (int kb = 0; kb < nk; kb++) {
        CP_WAIT(2);
        __syncthreads();

        uint32_t sA = sb + s * GSTAGE;
        uint32_t sB = sA + GTILE;

        #pragma unroll
        for (int kc = 0; kc < 2; kc++) {
            uint32_t a[2][4];
            #pragma unroll
            for (int mt = 0; mt < 2; mt++)
                ldsm4(a[mt], sA + aoff + mt * 16 * GSTR + kc * 32);
            #pragma unroll
            for (int p = 0; p < 4; p++) {
                uint32_t b4[4];
                ldsm4(b4, sB + boff + p * 16 * GSTR + kc * 32);
                mma_f16(acc[0][2 * p],     a[0], b4[0], b4[1]);
                mma_f16(acc[1][2 * p],     a[1], b4[0], b4[1]);
                mma_f16(acc[0][2 * p + 1], a[0], b4[2], b4[3]);
                mma_f16(acc[1][2 * p + 1], a[1], b4[2], b4[3]);
            }
        }

        if (kb + 3 < nk) load_stage(ls, kb + 3);
        CP_COMMIT();
        s  = (s  + 1) & 3;
        ls = (ls + 1) & 3;
    }

    // ---- staged epilogue (smem -> coalesced 16B stores) ----
    CP_WAIT(0);
    __syncthreads();

    if (HALF_OUT) {
        #pragma unroll
        for (int mt = 0; mt < 2; mt++) {
            const int r = wm * 32 + mt * 16 + g;
            #pragma unroll
            for (int nt = 0; nt < 8; nt++) {
                const int c = wn * 64 + nt * 8 + 2 * t4;
                *(uint32_t*)(smc + r * EPI_H_STR + c * 2) =
                    packh(acc[mt][nt][1], acc[mt][nt][0]);
                *(uint32_t*)(smc + (r + 8) * EPI_H_STR + c * 2) =
                    packh(acc[mt][nt][3], acc[mt][nt][2]);
            }
        }
        __syncthreads();
        #pragma unroll
        for (int it = 0; it < 8; it++) {
            int task = it * 256 + tid;        // 2048 tasks
            int row = task >> 4, ch = task & 15;
            uint4 v = *(const uint4*)(smc + row * EPI_H_STR + ch * 16);
            *(uint4*)(Ch + (size_t)(m0 + row) * N + n0 + ch * 8) = v;
        }
    } else {
        #pragma unroll
        for (int mt = 0; mt < 2; mt++) {
            const int r = wm * 32 + mt * 16 + g;
            #pragma unroll
            for (int nt = 0; nt < 8; nt++) {
                const int c = wn * 64 + nt * 8 + 2 * t4;
                *(float2*)(smc + r * EPI_F_STR + c * 4) =
                    make_float2(acc[mt][nt][0], acc[mt][nt][1]);
                *(float2*)(smc + (r + 8) * EPI_F_STR + c * 4) =
                    make_float2(acc[mt][nt][2], acc[mt][nt][3]);
            }
        }
        __syncthreads();
        #pragma unroll
        for (int it = 0; it < 16; it++) {
            int task = it * 256 + tid;        // 4096 tasks
            int row = task >> 5, ch = task & 31;
            uint4 v = *(const uint4*)(smc + row * EPI_F_STR + ch * 16);
            *(uint4*)(Cf + (size_t)(m0 + row) * N + n0 + ch * 4) = v;
        }
    }
}

// ===================== flash attention, single-fp16 Q/K/V =====================
// Br=128 (8 warps x 16 rows), Bc=64. 4-stage KV ring.
#define ATILE   (64 * 128)              // 8192
#define AQ      (128 * 128)             // 16384
#define ASTAGE  (2 * ATILE)             // 16384 (K, V)
#define ATT_SMEM (AQ + 4 * ASTAGE)      // 81920 -> 2 CTA/SM
#define AEPI_STR 144

__global__ __launch_bounds__(256, 2) void attn_mma(
    const __half* __restrict__ qkvh, __half* __restrict__ oh) {
    extern __shared__ char smc[];
    const uint32_t sb = smem_u32(smc);
    const int tid = threadIdx.x;
    const int w = tid >> 5, lane = tid & 31;
    const int g = lane >> 2, t4 = lane & 3;
    const int i8 = lane & 7, mq = lane >> 3;
    const int qblk = (int)gridDim.x - 1 - (int)blockIdx.x;   // heavy CTAs first
    const int h = blockIdx.y, b = blockIdx.z;
    const int nkt = 2 * qblk + 2;
    const float CS = 0.18033688011112042f;                   // 0.125 * log2(e)
    const float NEGINF = -INFINITY;

    auto load_q = [&]() {
        #pragma unroll
        for (int it = 0; it < 4; it++) {
            int task = it * 256 + tid;       // 0..1023
            int row = task >> 3, ch = task & 7;
            cp_async16(sb + row * 128 + ((ch ^ (row & 7)) * 16),
                       qkvh + ((size_t)(b * T_ + qblk * 128 + row)) * (3 * C_) + h * HD_ + ch * 8);
        }
    };
    auto load_kv = [&](int s, int kt) {
        #pragma unroll
        for (int it = 0; it < 4; it++) {
            int task = it * 256 + tid;       // 0..1023
            int mat = task >> 9;             // 0 K, 1 V
            int rem = task & 511;
            int row = rem >> 3, ch = rem & 7;
            int colbase = ((mat == 0) ? C_ : 2 * C_) + h * HD_;
            cp_async16(sb + AQ + s * ASTAGE + mat * ATILE + row * 128 + ((ch ^ (row & 7)) * 16),
                       qkvh + ((size_t)(b * T_ + kt * 64 + row)) * (3 * C_) + colbase + ch * 8);
        }
    };

    load_q(); load_kv(0, 0); CP_COMMIT();
    load_kv(1, 1); CP_COMMIT();
    if (nkt > 2) load_kv(2, 2);
    CP_COMMIT();
    CP_WAIT(2);
    __syncthreads();

    uint32_t qh[4][4];
    {
        const uint32_t qrow = (uint32_t)((w * 16 + (mq & 1) * 8 + i8) * 128);
        #pragma unroll
        for (int kc = 0; kc < 4; kc++)
            ldsm4(qh[kc], sb + qrow + ((((mq >> 1) + 2 * kc) ^ i8) * 16));
    }

    float O[8][4];
    #pragma unroll
    for (int nt = 0; nt < 8; nt++)
        #pragma unroll
        for (int i = 0; i < 4; i++) O[nt][i] = 0.f;
    float mcs0 = NEGINF, mcs1 = NEGINF, lsum0 = 0.f, lsum1 = 0.f;
    const int qrow0 = qblk * 128 + w * 16 + g;
    const int qrow1 = qrow0 + 8;

    const uint32_t krow = (uint32_t)(((mq >> 1) * 8 + i8) * 128);
    const uint32_t vrow = (uint32_t)(((mq & 1) * 8 + i8) * 128);

    int st = 0, ls = 3;
    for (int kb = 0; kb < nkt; kb++) {
        if (kb > 0) {
            CP_WAIT(2);
            __syncthreads();
        }
        uint32_t sKH = sb + AQ + st * ASTAGE;
        uint32_t sVH = sKH + ATILE;

        // ---- S = Q K^T ----
        float S[8][4];
        #pragma unroll
        for (int nt = 0; nt < 8; nt++)
            #pragma unroll
            for (int i = 0; i < 4; i++) S[nt][i] = 0.f;

        #pragma unroll
        for (int kc = 0; kc < 4; kc++) {
            const uint32_t kcol = (uint32_t)((((mq & 1) + 2 * kc) ^ i8) * 16);
            #pragma unroll
            for (int p = 0; p < 4; p++) {
                uint32_t kh4[4];
                ldsm4(kh4, sKH + krow + p * 16 * 128 + kcol);
                mma_f16(S[2 * p],     qh[kc], kh4[0], kh4[1]);
                mma_f16(S[2 * p + 1], qh[kc], kh4[2], kh4[3]);
            }
        }

        // ---- causal mask ----
        const int kbase = kb * 64;
        if (kbase + 63 > qrow0) {
            #pragma unroll
            for (int nt = 0; nt < 8; nt++) {
                int kc0 = kbase + nt * 8 + 2 * t4;
                if (kc0 > qrow0)     S[nt][0] = NEGINF;
                if (kc0 + 1 > qrow0) S[nt][1] = NEGINF;
                if (kc0 > qrow1)     S[nt][2] = NEGINF;
                if (kc0 + 1 > qrow1) S[nt][3] = NEGINF;
            }
        }

        // ---- online softmax (base-2) ----
        float mx0 = NEGINF, mx1 = NEGINF;
        #pragma unroll
        for (int nt = 0; nt < 8; nt++) {
            mx0 = fmaxf(mx0, fmaxf(S[nt][0], S[nt][1]));
            mx1 = fmaxf(mx1, fmaxf(S[nt][2], S[nt][3]));
        }
        mx0 = fmaxf(mx0, __shfl_xor_sync(0xffffffffu, mx0, 1));
        mx0 = fmaxf(mx0, __shfl_xor_sync(0xffffffffu, mx0, 2));
        mx1 = fmaxf(mx1, __shfl_xor_sync(0xffffffffu, mx1, 1));
        mx1 = fmaxf(mx1, __shfl_xor_sync(0xffffffffu, mx1, 2));
        float mn0 = fmaxf(mcs0, mx0 * CS);
        float mn1 = fmaxf(mcs1, mx1 * CS);
        float a0 = ex2(mcs0 - mn0);
        float a1 = ex2(mcs1 - mn1);
        mcs0 = mn0; mcs1 = mn1;

        float s0 = 0.f, s1 = 0.f;
        #pragma unroll
        for (int nt = 0; nt < 8; nt++) {
            S[nt][0] = ex2(fmaf(S[nt][0], CS, -mcs0)); s0 += S[nt][0];
            S[nt][1] = ex2(fmaf(S[nt][1], CS, -mcs0)); s0 += S[nt][1];
            S[nt][2] = ex2(fmaf(S[nt][2], CS, -mcs1)); s1 += S[nt][2];
            S[nt][3] = ex2(fmaf(S[nt][3], CS, -mcs1)); s1 += S[nt][3];
        }
        s0 += __shfl_xor_sync(0xffffffffu, s0, 1);
        s0 += __shfl_xor_sync(0xffffffffu, s0, 2);
        s1 += __shfl_xor_sync(0xffffffffu, s1, 1);
        s1 += __shfl_xor_sync(0xffffffffu, s1, 2);
        lsum0 = lsum0 * a0 + s0;
        lsum1 = lsum1 * a1 + s1;
        #pragma unroll
        for (int nt = 0; nt < 8; nt++) {
            O[nt][0] *= a0; O[nt][1] *= a0;
            O[nt][2] *= a1; O[nt][3] *= a1;
        }

        // ---- P (fp16 a-frags) then O += P V ----
        #pragma unroll
        for (int j = 0; j < 4; j++) {
            uint32_t ph[4];
            ph[0] = packh(S[2 * j][1],     S[2 * j][0]);
            ph[1] = packh(S[2 * j][3],     S[2 * j][2]);
            ph[2] = packh(S[2 * j + 1][1], S[2 * j + 1][0]);
            ph[3] = packh(S[2 * j + 1][3], S[2 * j + 1][2]);
            #pragma unroll
            for (int p = 0; p < 4; p++) {
                const uint32_t vcol = (uint32_t)((((mq >> 1) + 2 * p) ^ i8) * 16);
                uint32_t vh4[4];
                ldsm4t(vh4, sVH + vrow + j * 16 * 128 + vcol);
                mma_f16(O[2 * p],     ph, vh4[0], vh4[1]);
                mma_f16(O[2 * p + 1], ph, vh4[2], vh4[3]);
            }
        }

        if (kb + 3 < nkt) load_kv(ls, kb + 3);
        CP_COMMIT();
        st = (st + 1) & 3;
        ls = (ls + 1) & 3;
    }

    // ---- staged epilogue ----
    const float rl0 = 1.0f / lsum0, rl1 = 1.0f / lsum1;
    __syncthreads();
    {
        const int r = w * 16 + g;
        #pragma unroll
        for (int nt = 0; nt < 8; nt++) {
            const int c = nt * 8 + 2 * t4;
            *(uint32_t*)(smc + r * AEPI_STR + c * 2) =
                packh(O[nt][1] * rl0, O[nt][0] * rl0);
            *(uint32_t*)(smc + (r + 8) * AEPI_STR + c * 2) =
                packh(O[nt][3] * rl1, O[nt][2] * rl1);
        }
    }
    __syncthreads();
    #pragma unroll
    for (int it = 0; it < 4; it++) {
        int task = it * 256 + tid;       // 1024 tasks
        int row = task >> 3, ch = task & 7;
        uint4 v = *(const uint4*)(smc + row * AEPI_STR + ch * 16);
        *(uint4*)(oh + ((size_t)(b * T_ + qblk * 128 + row)) * C_ + h * HD_ + ch * 8) = v;
    }
}

// ===================== launch =====================
extern "C" void kernel_launch(void* const* d_in, const int* in_sizes, int n_in,
                              void* d_out, int out_size) {
    (void)in_sizes; (void)n_in; (void)out_size;
    const float* x      = (const float*)d_in[0];
    const float* w_qkv  = (const float*)d_in[1];
    const float* w_proj = (const float*)d_in[2];
    float* out = (float*)d_out;

    __half *xh, *wqh, *wph, *qkvh, *atth;
    cudaGetSymbolAddress((void**)&xh, g_xh);
    cudaGetSymbolAddress((void**)&wqh, g_wqh);
    cudaGetSymbolAddress((void**)&wph, g_wph);
    cudaGetSymbolAddress((void**)&qkvh, g_qkvh);
    cudaGetSymbolAddress((void**)&atth, g_atth);

    cudaFuncSetAttribute((const void*)gemm_f16<true>,
                         cudaFuncAttributeMaxDynamicSharedMemorySize, GEMM_SMEM);
    cudaFuncSetAttribute((const void*)gemm_f16<false>,
                         cudaFuncAttributeMaxDynamicSharedMemorySize, GEMM_SMEM);
    cudaFuncSetAttribute((const void*)attn_mma,
                         cudaFuncAttributeMaxDynamicSharedMemorySize, ATT_SMEM);

    // 0) fused input split (all single fp16)
    {
        int total = N4_X + N4_WQ + N4_WP;
        split_all<<<(total + 255) / 256, 256>>>(
            (const float4*)x, (const float4*)w_qkv, (const float4*)w_proj,
            (uint2*)xh, (uint2*)wqh, (uint2*)wph);
    }

    // 1) qkv = x @ w_qkv^T  -> fp16 out (Cf unused)
    gemm_f16<true><<<dim3(3 * C_ / 128, M_ / 128), 256, GEMM_SMEM>>>(
        xh, wqh, nullptr, qkvh, M_, 3 * C_, C_);

    // 2) attention -> fp16
    attn_mma<<<dim3(T_ / 128, H_, B_), 256, ATT_SMEM>>>(qkvh, atth);

    // 3) out = att @ w_proj^T  -> fp32 out (Ch unused)
    gemm_f16<false><<<dim3(C_ / 128, M_ / 128), 256, GEMM_SMEM>>>(
        atth, wph, out, nullptr, M_, C_, C_);
}